// round 7
// baseline (speedup 1.0000x reference)
#include <cuda_runtime.h>
#include <math.h>

#define IMG_H 800.0f
#define IMG_W 1280.0f
#define FSCALE (1.0f/16.0f)
#define PP 14
#define NUM_CLASSES 80
#define SCORE_TH 0.05f
#define NMS_TH 0.5f
#define MAX_DET 100
#define IOU_TH 0.5f
#define SCALE_CLAMP 4.135166556742356f
#define FH 50
#define FW 80
#define FC 1024
#define NIMG 2
#define NR 256
#define NGT 64
#define NPROP (NIMG * NR)          // 512
#define NCOL 96                    // 0..80 cls logits, 81..84 box deltas
#define NLOG 85
#define KSPLIT 8
#define KSLICE (FC / KSPLIT)       // 128
#define MTILE 32

// Scratch (device globals; no allocation allowed)
__device__ float g_featvecT[FC * NPROP];            // [k][prop]
__device__ float g_wy[NPROP * FH];
__device__ float g_wx[NPROP * FW];
__device__ int   g_bnd[NPROP * 4];                  // ylo,yhi,xlo,xhi
__device__ float g_part[KSPLIT * NCOL * NPROP];     // [ks][col][prop]

// ---------------------------------------------------------------------------
// Kernel 1: fused match + separable ROIAlign weight tables.
// grid(8, 2): 32 boxes per block, block(256). Per box: sub 0 = y-table,
// sub 1 = x-table, sub 2 = GT matching.
// ---------------------------------------------------------------------------
__global__ void weight_kernel(const float* __restrict__ prop,
                              const float* __restrict__ gt,
                              float* __restrict__ out_idx,
                              float* __restrict__ out_lbl) {
    int n = blockIdx.y;
    int b0 = blockIdx.x * 32;
    int t = threadIdx.x;

    __shared__ float wy[32 * FH];
    __shared__ float wx[32 * FW];

    for (int i = t; i < 32 * FH; i += 256) wy[i] = 0.0f;
    for (int i = t; i < 32 * FW; i += 256) wx[i] = 0.0f;
    __syncthreads();

    int b = t >> 3;
    int sub = t & 7;
    int box = b0 + b;
    const float* p = prop + (n * NR + box) * 4;

    if (sub == 0) {
        float y1 = p[1] * FSCALE, y2 = p[3] * FSCALE;
        float bh = (y2 - y1) * (1.0f / (float)PP);
        int lo = FH, hi = 0;
        for (int py = 0; py < PP; py++) {
            float gy = y1 + ((float)py + 0.5f) * bh - 0.5f;
            gy = fminf(fmaxf(gy, 0.0f), (float)(FH - 1));
            float y0 = floorf(gy);
            int y0i = (int)y0;
            int y1i = min(y0i + 1, FH - 1);
            float ly = gy - y0;
            wy[b * FH + y0i] += 1.0f - ly;
            wy[b * FH + y1i] += ly;
            lo = min(lo, y0i);
            hi = max(hi, y1i);
        }
        g_bnd[(n * NR + box) * 4 + 0] = lo;
        g_bnd[(n * NR + box) * 4 + 1] = hi;
    } else if (sub == 1) {
        float x1 = p[0] * FSCALE, x2 = p[2] * FSCALE;
        float bw = (x2 - x1) * (1.0f / (float)PP);
        int lo = FW, hi = 0;
        for (int px = 0; px < PP; px++) {
            float gx = x1 + ((float)px + 0.5f) * bw - 0.5f;
            gx = fminf(fmaxf(gx, 0.0f), (float)(FW - 1));
            float x0 = floorf(gx);
            int x0i = (int)x0;
            int x1i = min(x0i + 1, FW - 1);
            float lx = gx - x0;
            wx[b * FW + x0i] += 1.0f - lx;
            wx[b * FW + x1i] += lx;
            lo = min(lo, x0i);
            hi = max(hi, x1i);
        }
        g_bnd[(n * NR + box) * 4 + 2] = lo;
        g_bnd[(n * NR + box) * 4 + 3] = hi;
    } else if (sub == 2) {
        float px1 = p[0], py1 = p[1], px2 = p[2], py2 = p[3];
        float pa = (px2 - px1) * (py2 - py1);
        float best = -1.0f;
        int bi = 0;
        for (int g = 0; g < NGT; g++) {
            const float* gb = gt + (n * NGT + g) * 4;
            float gx1 = gb[0], gy1 = gb[1], gx2 = gb[2], gy2 = gb[3];
            float ga = (gx2 - gx1) * (gy2 - gy1);
            float lx = fmaxf(gx1, px1), ly = fmaxf(gy1, py1);
            float rx = fminf(gx2, px2), ry = fminf(gy2, py2);
            float w = fmaxf(rx - lx, 0.0f), h = fmaxf(ry - ly, 0.0f);
            float inter = w * h;
            float iou = inter / fmaxf(ga + pa - inter, 1e-9f);
            if (iou > best) { best = iou; bi = g; }
        }
        out_idx[n * NR + box] = (float)bi;
        out_lbl[n * NR + box] = (best >= IOU_TH) ? 1.0f : 0.0f;
    }
    __syncthreads();

    for (int i = t; i < 32 * FH; i += 256) g_wy[(n * NR + b0) * FH + i] = wy[i];
    for (int i = t; i < 32 * FW; i += 256) g_wx[(n * NR + b0) * FW + i] = wx[i];
}

// ---------------------------------------------------------------------------
// Kernel 2: ROIAlign via shared feature slice (4 channels/block).
// grid(FC/4=256, 2), block(256), dyn smem 62.5KB -> 3 blocks/SM.
// Output transposed: featvecT[k][prop] (coalesced writes over prop).
// ---------------------------------------------------------------------------
__global__ void roi_kernel(const float* __restrict__ feat,
                           float* __restrict__ featvecT) {
    extern __shared__ float sl[];           // [FH*FW][4]
    int c0 = blockIdx.x * 4;
    int n = blockIdx.y;
    int t = threadIdx.x;

    const float* fbase = feat + (size_t)n * FH * FW * FC + c0;
    for (int idx = t; idx < FH * FW; idx += 256) {
        float4 a = *(const float4*)(fbase + (size_t)idx * FC);
        *(float4*)(sl + idx * 4) = a;
    }
    __syncthreads();

    int box = t;
    int gid = n * NR + box;
    const int4 bnd = *(const int4*)&g_bnd[gid * 4];
    int ylo = bnd.x, yhi = bnd.y, xlo = bnd.z, xhi = bnd.w;
    const float* wyp = &g_wy[gid * FH];
    const float* wxp = &g_wx[gid * FW];

    float4 acc = make_float4(0.f, 0.f, 0.f, 0.f);

    for (int y = ylo; y <= yhi; y++) {
        float wyv = wyp[y];
        const float* rowp = sl + (y * FW) * 4;
        for (int x = xlo; x <= xhi; x++) {
            float w = wyv * wxp[x];
            float4 v = *(const float4*)(rowp + x * 4);
            acc.x += w * v.x;
            acc.y += w * v.y;
            acc.z += w * v.z;
            acc.w += w * v.w;
        }
    }
    const float inv = 1.0f / (float)(PP * PP);
    featvecT[(size_t)(c0 + 0) * NPROP + gid] = acc.x * inv;
    featvecT[(size_t)(c0 + 1) * NPROP + gid] = acc.y * inv;
    featvecT[(size_t)(c0 + 2) * NPROP + gid] = acc.z * inv;
    featvecT[(size_t)(c0 + 3) * NPROP + gid] = acc.w * inv;
}

// ---------------------------------------------------------------------------
// Kernel 3: head GEMM, smem-tiled + split-K, transposed sf.
// grid(16, 8), block(256), 64KB dyn smem.
// smem: sfT [128k][32props], W [128k][96cols]. Warp = propg (4 props),
// lane = colg. Per k: 1 broadcast LDS.128 (4 props) + 3 stride-1 LDS.32 (W)
// feed 12 FMA. Partials stored [ks][col][prop] via STG.128.
// ---------------------------------------------------------------------------
__global__ void gemm_kernel(const float* __restrict__ featvecT,
                            const float* __restrict__ Wc,
                            const float* __restrict__ Wb) {
    extern __shared__ float sm[];
    float* sfS = sm;                 // [128][32]
    float* wS = sm + KSLICE * MTILE; // [128][96]

    int t = threadIdx.x;
    int p0 = blockIdx.x * MTILE;
    int k0 = blockIdx.y * KSLICE;

    for (int i = t; i < KSLICE * MTILE; i += 256) {
        int k = i >> 5;
        int p = i & 31;
        sfS[i] = featvecT[(size_t)(k0 + k) * NPROP + p0 + p];
    }
    for (int i = t; i < KSLICE * NCOL; i += 256) {
        int r = i / NCOL;
        int c = i - r * NCOL;
        float v = 0.0f;
        if (c < NUM_CLASSES + 1) v = Wc[(size_t)(k0 + r) * (NUM_CLASSES + 1) + c];
        else if (c < NUM_CLASSES + 5) v = Wb[(size_t)(k0 + r) * 4 + (c - 81)];
        wS[i] = v;
    }
    __syncthreads();

    int colg = t & 31;
    int propg = t >> 5;              // 0..7

    float a00 = 0.f, a01 = 0.f, a02 = 0.f;
    float a10 = 0.f, a11 = 0.f, a12 = 0.f;
    float a20 = 0.f, a21 = 0.f, a22 = 0.f;
    float a30 = 0.f, a31 = 0.f, a32 = 0.f;

    #pragma unroll 4
    for (int k = 0; k < KSLICE; k++) {
        float4 s = *(const float4*)&sfS[k * MTILE + propg * 4];
        float w0 = wS[k * NCOL + colg];
        float w1 = wS[k * NCOL + colg + 32];
        float w2 = wS[k * NCOL + colg + 64];
        a00 += s.x * w0; a01 += s.x * w1; a02 += s.x * w2;
        a10 += s.y * w0; a11 += s.y * w1; a12 += s.y * w2;
        a20 += s.z * w0; a21 += s.z * w1; a22 += s.z * w2;
        a30 += s.w * w0; a31 += s.w * w1; a32 += s.w * w2;
    }

    float* base = g_part + (size_t)blockIdx.y * NCOL * NPROP + p0 + propg * 4;
    *(float4*)(base + (size_t)colg * NPROP) = make_float4(a00, a10, a20, a30);
    *(float4*)(base + (size_t)(colg + 32) * NPROP) = make_float4(a01, a11, a21, a31);
    *(float4*)(base + (size_t)(colg + 64) * NPROP) = make_float4(a02, a12, a22, a32);
}

// ---------------------------------------------------------------------------
// Kernel 4: fused reduce + softmax + decode + NMS + det write.
// grid(2), block(256), ~106KB dyn smem. Thread t = proposal t of image n:
// reduces 8 split-K partials per logit (coalesced over props), softmax fg
// score, box decode; then bitmatrix NMS + stable rank<100.
// ---------------------------------------------------------------------------
__global__ void nms_kernel(const float* __restrict__ prop,
                           const float* __restrict__ bc,
                           const float* __restrict__ bb,
                           float* __restrict__ det) {
    extern __shared__ float dsm[];
    float* slogS = dsm;                                   // 256*85
    float4* sbO = (float4*)(dsm + NR * NLOG);             // 256 (orig order)
    float4* sb = sbO + NR;                                // 256 (sorted)
    float* ss = (float*)(sb + NR);                        // 256
    float* smask = ss + NR;                               // 256
    int* order = (int*)(smask + NR);                      // 256
    unsigned int* supmask = (unsigned int*)(order + NR);  // 256*8
    unsigned int* keptw = supmask + NR * 8;               // 8

    int n = blockIdx.x;
    int t = threadIdx.x;
    int gid = n * NR + t;

    // reduce split-K partials (+bias) into logits; track class max
    float m = -INFINITY;
    for (int c = 0; c < NLOG; c++) {
        float s = 0.0f;
        #pragma unroll
        for (int ks = 0; ks < KSPLIT; ks++)
            s += g_part[(size_t)ks * NCOL * NPROP + (size_t)c * NPROP + gid];
        s += (c < NUM_CLASSES + 1) ? bc[c] : bb[c - 81];
        slogS[t * NLOG + c] = s;
        if (c <= NUM_CLASSES) m = fmaxf(m, s);
    }

    // softmax fg score
    float ssum = 0.0f;
    float fg = -INFINITY;
    for (int c = 0; c <= NUM_CLASSES; c++) {
        float e = expf(slogS[t * NLOG + c] - m);
        ssum += e;
        if (c < NUM_CLASSES) fg = fmaxf(fg, e);
    }
    float s_i = fg / ssum;
    ss[t] = s_i;

    // box decode
    {
        const float* p = prop + (size_t)gid * 4;
        float px1 = p[0], py1 = p[1], px2 = p[2], py2 = p[3];
        float wdt = px2 - px1, hgt = py2 - py1;
        float cx = px1 + 0.5f * wdt, cy = py1 + 0.5f * hgt;
        float dx = slogS[t * NLOG + 81] * 0.1f;
        float dy = slogS[t * NLOG + 82] * 0.1f;
        float dw = fminf(slogS[t * NLOG + 83] * 0.2f, SCALE_CLAMP);
        float dh = fminf(slogS[t * NLOG + 84] * 0.2f, SCALE_CLAMP);
        float pcx = dx * wdt + cx;
        float pcy = dy * hgt + cy;
        float pw = expf(dw) * wdt;
        float ph = expf(dh) * hgt;
        float4 ob;
        ob.x = fminf(fmaxf(pcx - 0.5f * pw, 0.0f), IMG_W);
        ob.y = fminf(fmaxf(pcy - 0.5f * ph, 0.0f), IMG_H);
        ob.z = fminf(fmaxf(pcx + 0.5f * pw, 0.0f), IMG_W);
        ob.w = fminf(fmaxf(pcy + 0.5f * ph, 0.0f), IMG_H);
        sbO[t] = ob;
    }
    __syncthreads();

    // stable descending rank
    int rk = 0;
    #pragma unroll 8
    for (int j = 0; j < NR; j++) {
        float sj = ss[j];
        rk += (sj > s_i) || (sj == s_i && j < t);
    }
    order[rk] = t;
    __syncthreads();

    sb[t] = sbO[order[t]];
    __syncthreads();

    // IoU bitmatrix row t (sorted order), multiply-compare (no FDIV)
    {
        float4 a = sb[t];
        float aa = (a.z - a.x) * (a.w - a.y);
        #pragma unroll
        for (int w = 0; w < 8; w++) {
            unsigned int word = 0;
            #pragma unroll 4
            for (int k = 0; k < 32; k++) {
                float4 b = sb[w * 32 + k];
                float ba = (b.z - b.x) * (b.w - b.y);
                float lx = fmaxf(a.x, b.x), ly = fmaxf(a.y, b.y);
                float rx = fminf(a.z, b.z), ry = fminf(a.w, b.w);
                float ww = fmaxf(rx - lx, 0.0f), hh = fmaxf(ry - ly, 0.0f);
                float inter = ww * hh;
                float u = fmaxf(aa + ba - inter, 1e-9f);
                if (inter > NMS_TH * u) word |= (1u << k);
            }
            supmask[t * 8 + w] = word;
        }
    }
    __syncthreads();

    // register greedy in warp 0
    if (t < 32) {
        unsigned kept[8];
        #pragma unroll
        for (int w = 0; w < 8; w++) kept[w] = 0u;
        #pragma unroll
        for (int w = 0; w < 8; w++) {
            int i = w * 32 + t;
            uint4 q0 = *(const uint4*)&supmask[i * 8];
            uint4 q1 = *(const uint4*)&supmask[i * 8 + 4];
            unsigned rw[8] = {q0.x, q0.y, q0.z, q0.w, q1.x, q1.y, q1.z, q1.w};
            unsigned msup = 0;
            #pragma unroll
            for (int w2 = 0; w2 < 8; w2++)
                if (w2 < w) msup |= rw[w2] & kept[w2];
            bool sup_prev = (msup != 0u);
            unsigned myw = rw[w];
            unsigned kw = 0u;
            #pragma unroll
            for (int k = 0; k < 32; k++) {
                bool keep_me = (!sup_prev) && ((myw & kw) == 0u);
                unsigned bmask = __ballot_sync(0xffffffffu, keep_me);
                kw |= (bmask & (1u << k));
            }
            kept[w] = kw;
        }
        #pragma unroll
        for (int w = 0; w < 8; w++)
            if (t == w) keptw[w] = kept[w];
    }
    __syncthreads();

    bool kp = (keptw[rk >> 5] >> (rk & 31)) & 1u;
    kp = kp && (s_i > SCORE_TH);
    smask[t] = kp ? s_i : -INFINITY;
    __syncthreads();

    int rank2 = 0;
    float mi = smask[t];
    #pragma unroll 8
    for (int j = 0; j < NR; j++) {
        float mj = smask[j];
        rank2 += (mj > mi) || (mj == mi && j < t);
    }
    kp = kp && (rank2 < MAX_DET);

    float4 ob = sbO[t];
    float* drow = det + (size_t)gid * 6;
    drow[0] = ob.x; drow[1] = ob.y;
    drow[2] = ob.z; drow[3] = ob.w;
    drow[4] = s_i;
    drow[5] = kp ? 1.0f : 0.0f;
}

// ---------------------------------------------------------------------------
extern "C" void kernel_launch(void* const* d_in, const int* in_sizes, int n_in,
                              void* d_out, int out_size) {
    const float* features = (const float*)d_in[0];
    const float* proposals = (const float*)d_in[1];
    const float* gt_boxes = (const float*)d_in[2];
    // d_in[3] = gt_classes (unused by reference)
    const float* W_cls = (const float*)d_in[4];
    const float* b_cls = (const float*)d_in[5];
    const float* W_box = (const float*)d_in[6];
    const float* b_box = (const float*)d_in[7];

    float* out = (float*)d_out;
    float* det = out;                          // 2*256*6 = 3072
    float* out_idx = out + NIMG * NR * 6;      // 512
    float* out_lbl = out_idx + NIMG * NR;      // 512

    float* featvecT; cudaGetSymbolAddress((void**)&featvecT, g_featvecT);

    const int ROI_SMEM = FH * FW * 4 * (int)sizeof(float);          // 64000 B
    const int GEMM_SMEM = (KSLICE * MTILE + KSLICE * NCOL) * 4;     // 65536 B
    const int NMS_SMEM = (NR * NLOG + NR * 4 * 2 + NR * 3 + NR * 8 + 8) * 4;
    cudaFuncSetAttribute(roi_kernel,
                         cudaFuncAttributeMaxDynamicSharedMemorySize, ROI_SMEM);
    cudaFuncSetAttribute(gemm_kernel,
                         cudaFuncAttributeMaxDynamicSharedMemorySize, GEMM_SMEM);
    cudaFuncSetAttribute(nms_kernel,
                         cudaFuncAttributeMaxDynamicSharedMemorySize, NMS_SMEM);

    weight_kernel<<<dim3(8, NIMG), 256>>>(proposals, gt_boxes, out_idx, out_lbl);
    roi_kernel<<<dim3(FC / 4, NIMG), 256, ROI_SMEM>>>(features, featvecT);
    gemm_kernel<<<dim3(NPROP / MTILE, KSPLIT), 256, GEMM_SMEM>>>(featvecT,
                                                                 W_cls, W_box);
    nms_kernel<<<NIMG, NR, NMS_SMEM>>>(proposals, b_cls, b_box, det);
}

// round 8
// speedup vs baseline: 1.1653x; 1.1653x over previous
#include <cuda_runtime.h>
#include <math.h>

#define IMG_H 800.0f
#define IMG_W 1280.0f
#define FSCALE (1.0f/16.0f)
#define PP 14
#define NUM_CLASSES 80
#define SCORE_TH 0.05f
#define NMS_TH 0.5f
#define MAX_DET 100
#define IOU_TH 0.5f
#define SCALE_CLAMP 4.135166556742356f
#define FH 50
#define FW 80
#define FC 1024
#define NIMG 2
#define NR 256
#define NGT 64
#define NPROP (NIMG * NR)          // 512
#define NCOL 96                    // padded output cols: 0..80 cls, 81..84 box
#define KSPLIT 8
#define KSLICE (FC / KSPLIT)       // 128
#define MTILE 32

// Scratch (device globals; no allocation allowed)
__device__ float g_featvec[NPROP * FC];
__device__ float g_boxes[NPROP * 4];
__device__ float g_scores[NPROP];
__device__ float g_wy[NPROP * FH];
__device__ float g_wx[NPROP * FW];
__device__ int   g_bnd[NPROP * 4];               // ylo,yhi,xlo,xhi
__device__ float g_part[KSPLIT * NPROP * NCOL];  // split-K partials

// ---------------------------------------------------------------------------
// Kernel 1: fused match + separable ROIAlign weight tables.
// grid(8, 2): 32 boxes per block, block(256). Per box: sub 0 = y-table,
// sub 1 = x-table, sub 2 = GT matching (all independent).
// ---------------------------------------------------------------------------
__global__ void weight_kernel(const float* __restrict__ prop,
                              const float* __restrict__ gt,
                              float* __restrict__ out_idx,
                              float* __restrict__ out_lbl) {
    int n = blockIdx.y;
    int b0 = blockIdx.x * 32;
    int t = threadIdx.x;

    __shared__ float wy[32 * FH];
    __shared__ float wx[32 * FW];

    for (int i = t; i < 32 * FH; i += 256) wy[i] = 0.0f;
    for (int i = t; i < 32 * FW; i += 256) wx[i] = 0.0f;
    __syncthreads();

    int b = t >> 3;          // box within block
    int sub = t & 7;
    int box = b0 + b;
    const float* p = prop + (n * NR + box) * 4;

    if (sub == 0) {
        float y1 = p[1] * FSCALE, y2 = p[3] * FSCALE;
        float bh = (y2 - y1) * (1.0f / (float)PP);
        int lo = FH, hi = 0;
        for (int py = 0; py < PP; py++) {
            float gy = y1 + ((float)py + 0.5f) * bh - 0.5f;
            gy = fminf(fmaxf(gy, 0.0f), (float)(FH - 1));
            float y0 = floorf(gy);
            int y0i = (int)y0;
            int y1i = min(y0i + 1, FH - 1);
            float ly = gy - y0;
            wy[b * FH + y0i] += 1.0f - ly;
            wy[b * FH + y1i] += ly;
            lo = min(lo, y0i);
            hi = max(hi, y1i);
        }
        g_bnd[(n * NR + box) * 4 + 0] = lo;
        g_bnd[(n * NR + box) * 4 + 1] = hi;
    } else if (sub == 1) {
        float x1 = p[0] * FSCALE, x2 = p[2] * FSCALE;
        float bw = (x2 - x1) * (1.0f / (float)PP);
        int lo = FW, hi = 0;
        for (int px = 0; px < PP; px++) {
            float gx = x1 + ((float)px + 0.5f) * bw - 0.5f;
            gx = fminf(fmaxf(gx, 0.0f), (float)(FW - 1));
            float x0 = floorf(gx);
            int x0i = (int)x0;
            int x1i = min(x0i + 1, FW - 1);
            float lx = gx - x0;
            wx[b * FW + x0i] += 1.0f - lx;
            wx[b * FW + x1i] += lx;
            lo = min(lo, x0i);
            hi = max(hi, x1i);
        }
        g_bnd[(n * NR + box) * 4 + 2] = lo;
        g_bnd[(n * NR + box) * 4 + 3] = hi;
    } else if (sub == 2) {
        float px1 = p[0], py1 = p[1], px2 = p[2], py2 = p[3];
        float pa = (px2 - px1) * (py2 - py1);
        float best = -1.0f;
        int bi = 0;
        for (int g = 0; g < NGT; g++) {
            const float* gb = gt + (n * NGT + g) * 4;
            float gx1 = gb[0], gy1 = gb[1], gx2 = gb[2], gy2 = gb[3];
            float ga = (gx2 - gx1) * (gy2 - gy1);
            float lx = fmaxf(gx1, px1), ly = fmaxf(gy1, py1);
            float rx = fminf(gx2, px2), ry = fminf(gy2, py2);
            float w = fmaxf(rx - lx, 0.0f), h = fmaxf(ry - ly, 0.0f);
            float inter = w * h;
            float iou = inter / fmaxf(ga + pa - inter, 1e-9f);
            if (iou > best) { best = iou; bi = g; }
        }
        out_idx[n * NR + box] = (float)bi;
        out_lbl[n * NR + box] = (best >= IOU_TH) ? 1.0f : 0.0f;
    }
    __syncthreads();

    for (int i = t; i < 32 * FH; i += 256) g_wy[(n * NR + b0) * FH + i] = wy[i];
    for (int i = t; i < 32 * FW; i += 256) g_wx[(n * NR + b0) * FW + i] = wx[i];
}

// ---------------------------------------------------------------------------
// Kernel 2: ROIAlign via shared feature slice (4 channels/block).
// grid(FC/4=256, 2), block(256), dyn smem 62.5KB -> 3 blocks/SM, 1 wave.
// Block loads its 50x80x4 slice ONCE, thread t = box t accumulates its
// weighted footprint from smem. Same math order as the 8ch version.
// ---------------------------------------------------------------------------
__global__ void roi_kernel(const float* __restrict__ feat,
                           float* __restrict__ featvec) {
    extern __shared__ float sl[];           // [FH*FW][4]
    int c0 = blockIdx.x * 4;
    int n = blockIdx.y;
    int t = threadIdx.x;

    const float* fbase = feat + (size_t)n * FH * FW * FC + c0;
    for (int idx = t; idx < FH * FW; idx += 256) {
        float4 a = *(const float4*)(fbase + (size_t)idx * FC);
        *(float4*)(sl + idx * 4) = a;
    }
    __syncthreads();

    int box = t;
    int gid = n * NR + box;
    const int4 bnd = *(const int4*)&g_bnd[gid * 4];
    int ylo = bnd.x, yhi = bnd.y, xlo = bnd.z, xhi = bnd.w;
    const float* wyp = &g_wy[gid * FH];
    const float* wxp = &g_wx[gid * FW];

    float4 acc = make_float4(0.f, 0.f, 0.f, 0.f);

    for (int y = ylo; y <= yhi; y++) {
        float wyv = wyp[y];
        const float* rowp = sl + (y * FW) * 4;
        for (int x = xlo; x <= xhi; x++) {
            float w = wyv * wxp[x];
            float4 v = *(const float4*)(rowp + x * 4);
            acc.x += w * v.x;
            acc.y += w * v.y;
            acc.z += w * v.z;
            acc.w += w * v.w;
        }
    }
    const float inv = 1.0f / (float)(PP * PP);
    acc.x *= inv; acc.y *= inv; acc.z *= inv; acc.w *= inv;
    *(float4*)(featvec + (size_t)gid * FC + c0) = acc;
}

// ---------------------------------------------------------------------------
// Kernel 3a: head GEMM, smem-tiled + split-K.
// grid(16, 8) = (M-tile of 32 props, K-slice of 128), block(256), 64KB smem.
// ---------------------------------------------------------------------------
__global__ void gemm_kernel(const float* __restrict__ featvec,
                            const float* __restrict__ Wc,
                            const float* __restrict__ Wb) {
    extern __shared__ float sm[];
    float* sfS = sm;                 // 32*128
    float* wS = sm + MTILE * KSLICE; // 128*96

    int t = threadIdx.x;
    int p0 = blockIdx.x * MTILE;
    int k0 = blockIdx.y * KSLICE;

    for (int i = t; i < MTILE * KSLICE; i += 256) {
        int p = i >> 7;          // /128
        int k = i & (KSLICE - 1);
        sfS[i] = featvec[(size_t)(p0 + p) * FC + k0 + k];
    }
    for (int i = t; i < KSLICE * NCOL; i += 256) {
        int r = i / NCOL;
        int c = i - r * NCOL;
        float v = 0.0f;
        if (c < NUM_CLASSES + 1) v = Wc[(size_t)(k0 + r) * (NUM_CLASSES + 1) + c];
        else if (c < NUM_CLASSES + 5) v = Wb[(size_t)(k0 + r) * 4 + (c - 81)];
        wS[i] = v;
    }
    __syncthreads();

    int colg = t & 31;
    int propg = t >> 5;              // 0..7
    const float* sfp = sfS + (propg * 4) * KSLICE;

    float a00 = 0.f, a01 = 0.f, a02 = 0.f;
    float a10 = 0.f, a11 = 0.f, a12 = 0.f;
    float a20 = 0.f, a21 = 0.f, a22 = 0.f;
    float a30 = 0.f, a31 = 0.f, a32 = 0.f;

    #pragma unroll 4
    for (int k = 0; k < KSLICE; k++) {
        float w0 = wS[k * NCOL + colg];
        float w1 = wS[k * NCOL + colg + 32];
        float w2 = wS[k * NCOL + colg + 64];
        float s0 = sfp[k];
        float s1 = sfp[KSLICE + k];
        float s2 = sfp[2 * KSLICE + k];
        float s3 = sfp[3 * KSLICE + k];
        a00 += s0 * w0; a01 += s0 * w1; a02 += s0 * w2;
        a10 += s1 * w0; a11 += s1 * w1; a12 += s1 * w2;
        a20 += s2 * w0; a21 += s2 * w1; a22 += s2 * w2;
        a30 += s3 * w0; a31 += s3 * w1; a32 += s3 * w2;
    }

    float* op = g_part + (size_t)blockIdx.y * NPROP * NCOL +
                (size_t)(p0 + propg * 4) * NCOL + colg;
    op[0] = a00; op[32] = a01; op[64] = a02;
    op += NCOL; op[0] = a10; op[32] = a11; op[64] = a12;
    op += NCOL; op[0] = a20; op[32] = a21; op[64] = a22;
    op += NCOL; op[0] = a30; op[32] = a31; op[64] = a32;
}

// ---------------------------------------------------------------------------
// Kernel 3b: reduce split-K partials + bias, softmax fg score, box decode.
// grid(512) one block per proposal, block(96).
// ---------------------------------------------------------------------------
__global__ void reduce_kernel(const float* __restrict__ prop,
                              const float* __restrict__ bc,
                              const float* __restrict__ bb,
                              float* __restrict__ boxes,
                              float* __restrict__ scores) {
    int gid = blockIdx.x;
    int t = threadIdx.x;
    __shared__ float slog[NUM_CLASSES + 5];

    if (t < NUM_CLASSES + 5) {
        float s = 0.0f;
        #pragma unroll
        for (int ks = 0; ks < KSPLIT; ks++)
            s += g_part[(size_t)ks * NPROP * NCOL + (size_t)gid * NCOL + t];
        if (t < NUM_CLASSES + 1) s += bc[t];
        else s += bb[t - 81];
        slog[t] = s;
    }
    __syncthreads();

    if (t == 0) {
        float m = -INFINITY;
        for (int c = 0; c <= NUM_CLASSES; c++) m = fmaxf(m, slog[c]);
        float ssum = 0.0f;
        float fg = -INFINITY;
        for (int c = 0; c <= NUM_CLASSES; c++) {
            float e = expf(slog[c] - m);
            ssum += e;
            if (c < NUM_CLASSES) fg = fmaxf(fg, e);
        }
        scores[gid] = fg / ssum;

        const float* p = prop + (size_t)gid * 4;
        float px1 = p[0], py1 = p[1], px2 = p[2], py2 = p[3];
        float wdt = px2 - px1, hgt = py2 - py1;
        float cx = px1 + 0.5f * wdt, cy = py1 + 0.5f * hgt;
        float dx = slog[81] * 0.1f;
        float dy = slog[82] * 0.1f;
        float dw = fminf(slog[83] * 0.2f, SCALE_CLAMP);
        float dh = fminf(slog[84] * 0.2f, SCALE_CLAMP);
        float pcx = dx * wdt + cx;
        float pcy = dy * hgt + cy;
        float pw = expf(dw) * wdt;
        float ph = expf(dh) * hgt;
        float* ob = boxes + (size_t)gid * 4;
        ob[0] = fminf(fmaxf(pcx - 0.5f * pw, 0.0f), IMG_W);
        ob[1] = fminf(fmaxf(pcy - 0.5f * ph, 0.0f), IMG_H);
        ob[2] = fminf(fmaxf(pcx + 0.5f * pw, 0.0f), IMG_W);
        ob[3] = fminf(fmaxf(pcy + 0.5f * ph, 0.0f), IMG_H);
    }
}

// ---------------------------------------------------------------------------
// Kernel 4: NMS + ranking + det write. grid(2), block(256).
// ---------------------------------------------------------------------------
__global__ void nms_kernel(const float* __restrict__ boxes,
                           const float* __restrict__ scores,
                           float* __restrict__ det) {
    int n = blockIdx.x;
    int t = threadIdx.x;

    __shared__ float ss[NR];
    __shared__ int order[NR];
    __shared__ float4 sb[NR];
    __shared__ unsigned int supmask[NR][8];
    __shared__ unsigned int keptw[8];
    __shared__ float smask[NR];

    float s_i = scores[n * NR + t];
    ss[t] = s_i;
    __syncthreads();

    int rk = 0;
    #pragma unroll 8
    for (int j = 0; j < NR; j++) {
        float sj = ss[j];
        rk += (sj > s_i) || (sj == s_i && j < t);
    }
    order[rk] = t;
    __syncthreads();

    sb[t] = ((const float4*)boxes)[n * NR + order[t]];
    __syncthreads();

    {
        float4 a = sb[t];
        float aa = (a.z - a.x) * (a.w - a.y);
        #pragma unroll
        for (int w = 0; w < 8; w++) {
            unsigned int word = 0;
            #pragma unroll 4
            for (int k = 0; k < 32; k++) {
                float4 b = sb[w * 32 + k];
                float ba = (b.z - b.x) * (b.w - b.y);
                float lx = fmaxf(a.x, b.x), ly = fmaxf(a.y, b.y);
                float rx = fminf(a.z, b.z), ry = fminf(a.w, b.w);
                float ww = fmaxf(rx - lx, 0.0f), hh = fmaxf(ry - ly, 0.0f);
                float inter = ww * hh;
                float u = fmaxf(aa + ba - inter, 1e-9f);
                if (inter > NMS_TH * u) word |= (1u << k);
            }
            supmask[t][w] = word;
        }
    }
    __syncthreads();

    if (t < 32) {
        unsigned kept[8];
        #pragma unroll
        for (int w = 0; w < 8; w++) kept[w] = 0u;
        #pragma unroll
        for (int w = 0; w < 8; w++) {
            int i = w * 32 + t;
            uint4 q0 = *(const uint4*)&supmask[i][0];
            uint4 q1 = *(const uint4*)&supmask[i][4];
            unsigned rw[8] = {q0.x, q0.y, q0.z, q0.w, q1.x, q1.y, q1.z, q1.w};
            unsigned m = 0;
            #pragma unroll
            for (int w2 = 0; w2 < 8; w2++)
                if (w2 < w) m |= rw[w2] & kept[w2];
            bool sup_prev = (m != 0u);
            unsigned myw = rw[w];
            unsigned kw = 0u;
            #pragma unroll
            for (int k = 0; k < 32; k++) {
                bool keep_me = (!sup_prev) && ((myw & kw) == 0u);
                unsigned b = __ballot_sync(0xffffffffu, keep_me);
                kw |= (b & (1u << k));
            }
            kept[w] = kw;
        }
        #pragma unroll
        for (int w = 0; w < 8; w++)
            if (t == w) keptw[w] = kept[w];
    }
    __syncthreads();

    bool kp = (keptw[rk >> 5] >> (rk & 31)) & 1u;
    kp = kp && (s_i > SCORE_TH);
    smask[t] = kp ? s_i : -INFINITY;
    __syncthreads();

    int rank2 = 0;
    float mi = smask[t];
    #pragma unroll 8
    for (int j = 0; j < NR; j++) {
        float mj = smask[j];
        rank2 += (mj > mi) || (mj == mi && j < t);
    }
    kp = kp && (rank2 < MAX_DET);

    const float* bsrc = boxes + (size_t)(n * NR + t) * 4;
    float* drow = det + (size_t)(n * NR + t) * 6;
    drow[0] = bsrc[0]; drow[1] = bsrc[1];
    drow[2] = bsrc[2]; drow[3] = bsrc[3];
    drow[4] = s_i;
    drow[5] = kp ? 1.0f : 0.0f;
}

// ---------------------------------------------------------------------------
extern "C" void kernel_launch(void* const* d_in, const int* in_sizes, int n_in,
                              void* d_out, int out_size) {
    const float* features = (const float*)d_in[0];
    const float* proposals = (const float*)d_in[1];
    const float* gt_boxes = (const float*)d_in[2];
    // d_in[3] = gt_classes (unused by reference)
    const float* W_cls = (const float*)d_in[4];
    const float* b_cls = (const float*)d_in[5];
    const float* W_box = (const float*)d_in[6];
    const float* b_box = (const float*)d_in[7];

    float* out = (float*)d_out;
    float* det = out;                          // 2*256*6 = 3072
    float* out_idx = out + NIMG * NR * 6;      // 512
    float* out_lbl = out_idx + NIMG * NR;      // 512

    float* featvec; cudaGetSymbolAddress((void**)&featvec, g_featvec);
    float* boxes;   cudaGetSymbolAddress((void**)&boxes, g_boxes);
    float* scores;  cudaGetSymbolAddress((void**)&scores, g_scores);

    const int ROI_SMEM = FH * FW * 4 * (int)sizeof(float);         // 64000 B
    const int GEMM_SMEM = (MTILE * KSLICE + KSLICE * NCOL) * 4;    // 65536 B
    cudaFuncSetAttribute(roi_kernel,
                         cudaFuncAttributeMaxDynamicSharedMemorySize, ROI_SMEM);
    cudaFuncSetAttribute(gemm_kernel,
                         cudaFuncAttributeMaxDynamicSharedMemorySize, GEMM_SMEM);

    weight_kernel<<<dim3(8, NIMG), 256>>>(proposals, gt_boxes, out_idx, out_lbl);
    roi_kernel<<<dim3(FC / 4, NIMG), 256, ROI_SMEM>>>(features, featvec);
    gemm_kernel<<<dim3(NPROP / MTILE, KSPLIT), 256, GEMM_SMEM>>>(featvec,
                                                                 W_cls, W_box);
    reduce_kernel<<<NPROP, 96>>>(proposals, b_cls, b_box, boxes, scores);
    nms_kernel<<<NIMG, NR>>>(boxes, scores, det);
}

// round 9
// speedup vs baseline: 1.4990x; 1.2864x over previous
#include <cuda_runtime.h>
#include <math.h>

#define IMG_H 800.0f
#define IMG_W 1280.0f
#define FSCALE (1.0f/16.0f)
#define PP 14
#define NUM_CLASSES 80
#define SCORE_TH 0.05f
#define NMS_TH 0.5f
#define MAX_DET 100
#define IOU_TH 0.5f
#define SCALE_CLAMP 4.135166556742356f
#define FH 50
#define FW 80
#define FC 1024
#define NIMG 2
#define NR 256
#define NGT 64
#define NPROP (NIMG * NR)          // 512
#define NCOL 96                    // padded output cols: 0..80 cls, 81..84 box
#define KSPLIT 8
#define KSLICE (FC / KSPLIT)       // 128
#define MTILE 32

// Scratch (device globals; no allocation allowed)
__device__ float g_featvec[NPROP * FC];
__device__ float g_boxes[NPROP * 4];
__device__ float g_scores[NPROP];
__device__ float g_wy[NPROP * FH];
__device__ float g_wx[NPROP * FW];
__device__ int   g_bnd[NPROP * 4];               // ylo,yhi,xlo,xhi
__device__ float g_part[KSPLIT * NPROP * NCOL];  // split-K partials
__device__ float g_sboxes[NPROP * 4];            // score-sorted boxes
__device__ int   g_rank[NPROP];                  // sorted position per proposal
__device__ unsigned int g_supmask[NPROP * 8];    // suppression bitmatrix

// ---------------------------------------------------------------------------
// Kernel 1: fused match + separable ROIAlign weight tables.
// grid(8, 2): 32 boxes per block, block(256). Per box: sub 0 = y-table,
// sub 1 = x-table, sub 2 = GT matching (all independent).
// ---------------------------------------------------------------------------
__global__ void weight_kernel(const float* __restrict__ prop,
                              const float* __restrict__ gt,
                              float* __restrict__ out_idx,
                              float* __restrict__ out_lbl) {
    int n = blockIdx.y;
    int b0 = blockIdx.x * 32;
    int t = threadIdx.x;

    __shared__ float wy[32 * FH];
    __shared__ float wx[32 * FW];

    for (int i = t; i < 32 * FH; i += 256) wy[i] = 0.0f;
    for (int i = t; i < 32 * FW; i += 256) wx[i] = 0.0f;
    __syncthreads();

    int b = t >> 3;          // box within block
    int sub = t & 7;
    int box = b0 + b;
    const float* p = prop + (n * NR + box) * 4;

    if (sub == 0) {
        float y1 = p[1] * FSCALE, y2 = p[3] * FSCALE;
        float bh = (y2 - y1) * (1.0f / (float)PP);
        int lo = FH, hi = 0;
        for (int py = 0; py < PP; py++) {
            float gy = y1 + ((float)py + 0.5f) * bh - 0.5f;
            gy = fminf(fmaxf(gy, 0.0f), (float)(FH - 1));
            float y0 = floorf(gy);
            int y0i = (int)y0;
            int y1i = min(y0i + 1, FH - 1);
            float ly = gy - y0;
            wy[b * FH + y0i] += 1.0f - ly;
            wy[b * FH + y1i] += ly;
            lo = min(lo, y0i);
            hi = max(hi, y1i);
        }
        g_bnd[(n * NR + box) * 4 + 0] = lo;
        g_bnd[(n * NR + box) * 4 + 1] = hi;
    } else if (sub == 1) {
        float x1 = p[0] * FSCALE, x2 = p[2] * FSCALE;
        float bw = (x2 - x1) * (1.0f / (float)PP);
        int lo = FW, hi = 0;
        for (int px = 0; px < PP; px++) {
            float gx = x1 + ((float)px + 0.5f) * bw - 0.5f;
            gx = fminf(fmaxf(gx, 0.0f), (float)(FW - 1));
            float x0 = floorf(gx);
            int x0i = (int)x0;
            int x1i = min(x0i + 1, FW - 1);
            float lx = gx - x0;
            wx[b * FW + x0i] += 1.0f - lx;
            wx[b * FW + x1i] += lx;
            lo = min(lo, x0i);
            hi = max(hi, x1i);
        }
        g_bnd[(n * NR + box) * 4 + 2] = lo;
        g_bnd[(n * NR + box) * 4 + 3] = hi;
    } else if (sub == 2) {
        float px1 = p[0], py1 = p[1], px2 = p[2], py2 = p[3];
        float pa = (px2 - px1) * (py2 - py1);
        float best = -1.0f;
        int bi = 0;
        for (int g = 0; g < NGT; g++) {
            const float* gb = gt + (n * NGT + g) * 4;
            float gx1 = gb[0], gy1 = gb[1], gx2 = gb[2], gy2 = gb[3];
            float ga = (gx2 - gx1) * (gy2 - gy1);
            float lx = fmaxf(gx1, px1), ly = fmaxf(gy1, py1);
            float rx = fminf(gx2, px2), ry = fminf(gy2, py2);
            float w = fmaxf(rx - lx, 0.0f), h = fmaxf(ry - ly, 0.0f);
            float inter = w * h;
            float iou = inter / fmaxf(ga + pa - inter, 1e-9f);
            if (iou > best) { best = iou; bi = g; }
        }
        out_idx[n * NR + box] = (float)bi;
        out_lbl[n * NR + box] = (best >= IOU_TH) ? 1.0f : 0.0f;
    }
    __syncthreads();

    for (int i = t; i < 32 * FH; i += 256) g_wy[(n * NR + b0) * FH + i] = wy[i];
    for (int i = t; i < 32 * FW; i += 256) g_wx[(n * NR + b0) * FW + i] = wx[i];
}

// ---------------------------------------------------------------------------
// Kernel 2: ROIAlign via shared feature slice (8 channels/block — R6 config).
// grid(FC/8=128, 2), block(256), dyn smem 125KB. Feature traffic = 33MB total.
// ---------------------------------------------------------------------------
__global__ void roi_kernel(const float* __restrict__ feat,
                           float* __restrict__ featvec) {
    extern __shared__ float sl[];           // [FH*FW][8]
    int c0 = blockIdx.x * 8;
    int n = blockIdx.y;
    int t = threadIdx.x;

    const float* fbase = feat + (size_t)n * FH * FW * FC + c0;
    for (int idx = t; idx < FH * FW; idx += 256) {
        const float4* src = (const float4*)(fbase + (size_t)idx * FC);
        float4 a = src[0];
        float4 b = src[1];
        float4* dst = (float4*)(sl + idx * 8);
        dst[0] = a;
        dst[1] = b;
    }
    __syncthreads();

    int box = t;
    const int4 bnd = *(const int4*)&g_bnd[(n * NR + box) * 4];
    int ylo = bnd.x, yhi = bnd.y, xlo = bnd.z, xhi = bnd.w;
    const float* wyp = &g_wy[(n * NR + box) * FH];
    const float* wxp = &g_wx[(n * NR + box) * FW];

    float4 acc0 = make_float4(0.f, 0.f, 0.f, 0.f);
    float4 acc1 = make_float4(0.f, 0.f, 0.f, 0.f);

    for (int y = ylo; y <= yhi; y++) {
        float wyv = wyp[y];
        const float* rowp = sl + (y * FW) * 8;
        for (int x = xlo; x <= xhi; x++) {
            float w = wyv * wxp[x];
            const float4* cell = (const float4*)(rowp + x * 8);
            float4 v0 = cell[0];
            float4 v1 = cell[1];
            acc0.x += w * v0.x; acc0.y += w * v0.y;
            acc0.z += w * v0.z; acc0.w += w * v0.w;
            acc1.x += w * v1.x; acc1.y += w * v1.y;
            acc1.z += w * v1.z; acc1.w += w * v1.w;
        }
    }
    const float inv = 1.0f / (float)(PP * PP);
    acc0.x *= inv; acc0.y *= inv; acc0.z *= inv; acc0.w *= inv;
    acc1.x *= inv; acc1.y *= inv; acc1.z *= inv; acc1.w *= inv;
    float4* out = (float4*)(featvec + (size_t)(n * NR + box) * FC + c0);
    out[0] = acc0;
    out[1] = acc1;
}

// ---------------------------------------------------------------------------
// Kernel 3a: head GEMM, smem-tiled + split-K.
// grid(16, 8) = (M-tile of 32 props, K-slice of 128), block(256), 64KB smem.
// ---------------------------------------------------------------------------
__global__ void gemm_kernel(const float* __restrict__ featvec,
                            const float* __restrict__ Wc,
                            const float* __restrict__ Wb) {
    extern __shared__ float sm[];
    float* sfS = sm;                 // 32*128
    float* wS = sm + MTILE * KSLICE; // 128*96

    int t = threadIdx.x;
    int p0 = blockIdx.x * MTILE;
    int k0 = blockIdx.y * KSLICE;

    for (int i = t; i < MTILE * KSLICE; i += 256) {
        int p = i >> 7;          // /128
        int k = i & (KSLICE - 1);
        sfS[i] = featvec[(size_t)(p0 + p) * FC + k0 + k];
    }
    for (int i = t; i < KSLICE * NCOL; i += 256) {
        int r = i / NCOL;
        int c = i - r * NCOL;
        float v = 0.0f;
        if (c < NUM_CLASSES + 1) v = Wc[(size_t)(k0 + r) * (NUM_CLASSES + 1) + c];
        else if (c < NUM_CLASSES + 5) v = Wb[(size_t)(k0 + r) * 4 + (c - 81)];
        wS[i] = v;
    }
    __syncthreads();

    int colg = t & 31;
    int propg = t >> 5;              // 0..7
    const float* sfp = sfS + (propg * 4) * KSLICE;

    float a00 = 0.f, a01 = 0.f, a02 = 0.f;
    float a10 = 0.f, a11 = 0.f, a12 = 0.f;
    float a20 = 0.f, a21 = 0.f, a22 = 0.f;
    float a30 = 0.f, a31 = 0.f, a32 = 0.f;

    #pragma unroll 4
    for (int k = 0; k < KSLICE; k++) {
        float w0 = wS[k * NCOL + colg];
        float w1 = wS[k * NCOL + colg + 32];
        float w2 = wS[k * NCOL + colg + 64];
        float s0 = sfp[k];
        float s1 = sfp[KSLICE + k];
        float s2 = sfp[2 * KSLICE + k];
        float s3 = sfp[3 * KSLICE + k];
        a00 += s0 * w0; a01 += s0 * w1; a02 += s0 * w2;
        a10 += s1 * w0; a11 += s1 * w1; a12 += s1 * w2;
        a20 += s2 * w0; a21 += s2 * w1; a22 += s2 * w2;
        a30 += s3 * w0; a31 += s3 * w1; a32 += s3 * w2;
    }

    float* op = g_part + (size_t)blockIdx.y * NPROP * NCOL +
                (size_t)(p0 + propg * 4) * NCOL + colg;
    op[0] = a00; op[32] = a01; op[64] = a02;
    op += NCOL; op[0] = a10; op[32] = a11; op[64] = a12;
    op += NCOL; op[0] = a20; op[32] = a21; op[64] = a22;
    op += NCOL; op[0] = a30; op[32] = a31; op[64] = a32;
}

// ---------------------------------------------------------------------------
// Kernel 3b: reduce split-K partials + bias, softmax fg score, box decode.
// grid(512) one block per proposal, block(96).
// ---------------------------------------------------------------------------
__global__ void reduce_kernel(const float* __restrict__ prop,
                              const float* __restrict__ bc,
                              const float* __restrict__ bb,
                              float* __restrict__ boxes,
                              float* __restrict__ scores) {
    int gid = blockIdx.x;
    int t = threadIdx.x;
    __shared__ float slog[NUM_CLASSES + 5];

    if (t < NUM_CLASSES + 5) {
        float s = 0.0f;
        #pragma unroll
        for (int ks = 0; ks < KSPLIT; ks++)
            s += g_part[(size_t)ks * NPROP * NCOL + (size_t)gid * NCOL + t];
        if (t < NUM_CLASSES + 1) s += bc[t];
        else s += bb[t - 81];
        slog[t] = s;
    }
    __syncthreads();

    if (t == 0) {
        float m = -INFINITY;
        for (int c = 0; c <= NUM_CLASSES; c++) m = fmaxf(m, slog[c]);
        float ssum = 0.0f;
        float fg = -INFINITY;
        for (int c = 0; c <= NUM_CLASSES; c++) {
            float e = expf(slog[c] - m);
            ssum += e;
            if (c < NUM_CLASSES) fg = fmaxf(fg, e);
        }
        scores[gid] = fg / ssum;

        const float* p = prop + (size_t)gid * 4;
        float px1 = p[0], py1 = p[1], px2 = p[2], py2 = p[3];
        float wdt = px2 - px1, hgt = py2 - py1;
        float cx = px1 + 0.5f * wdt, cy = py1 + 0.5f * hgt;
        float dx = slog[81] * 0.1f;
        float dy = slog[82] * 0.1f;
        float dw = fminf(slog[83] * 0.2f, SCALE_CLAMP);
        float dh = fminf(slog[84] * 0.2f, SCALE_CLAMP);
        float pcx = dx * wdt + cx;
        float pcy = dy * hgt + cy;
        float pw = expf(dw) * wdt;
        float ph = expf(dh) * hgt;
        float* ob = boxes + (size_t)gid * 4;
        ob[0] = fminf(fmaxf(pcx - 0.5f * pw, 0.0f), IMG_W);
        ob[1] = fminf(fmaxf(pcy - 0.5f * ph, 0.0f), IMG_H);
        ob[2] = fminf(fmaxf(pcx + 0.5f * pw, 0.0f), IMG_W);
        ob[3] = fminf(fmaxf(pcy + 0.5f * ph, 0.0f), IMG_H);
    }
}

// ---------------------------------------------------------------------------
// Kernel 4a: stable descending sort rank + sorted box gather. grid(2), b(256).
// ---------------------------------------------------------------------------
__global__ void sort_kernel(const float* __restrict__ boxes,
                            const float* __restrict__ scores) {
    int n = blockIdx.x;
    int t = threadIdx.x;
    int gid = n * NR + t;

    __shared__ float ss[NR];
    __shared__ int order[NR];

    float s_i = scores[gid];
    ss[t] = s_i;
    __syncthreads();

    int rk = 0;
    #pragma unroll 8
    for (int j = 0; j < NR; j++) {
        float sj = ss[j];
        rk += (sj > s_i) || (sj == s_i && j < t);
    }
    g_rank[gid] = rk;
    order[rk] = t;
    __syncthreads();

    ((float4*)g_sboxes)[gid] = ((const float4*)boxes)[n * NR + order[t]];
}

// ---------------------------------------------------------------------------
// Kernel 4b: IoU suppression bitmatrix. grid(8, 2), block(256).
// Thread = one 32-bit word: row r = bx*32 + t/8, word w = t%8 (coalesced STG).
// Multiply-compare, no FDIV. 16 blocks spread the O(R^2) work across SMs.
// ---------------------------------------------------------------------------
__global__ void iou_kernel() {
    __shared__ float4 sb[NR];
    int n = blockIdx.y;
    int t = threadIdx.x;

    for (int i = t; i < NR; i += 256) sb[i] = ((const float4*)g_sboxes)[n * NR + i];
    __syncthreads();

    int r = blockIdx.x * 32 + (t >> 3);
    int w = t & 7;

    float4 a = sb[r];
    float aa = (a.z - a.x) * (a.w - a.y);
    unsigned int word = 0;
    #pragma unroll 8
    for (int k = 0; k < 32; k++) {
        float4 b = sb[w * 32 + k];
        float ba = (b.z - b.x) * (b.w - b.y);
        float lx = fmaxf(a.x, b.x), ly = fmaxf(a.y, b.y);
        float rx = fminf(a.z, b.z), ry = fminf(a.w, b.w);
        float ww = fmaxf(rx - lx, 0.0f), hh = fmaxf(ry - ly, 0.0f);
        float inter = ww * hh;
        float u = fmaxf(aa + ba - inter, 1e-9f);
        if (inter > NMS_TH * u) word |= (1u << k);
    }
    g_supmask[(n * NR + r) * 8 + w] = word;
}

// ---------------------------------------------------------------------------
// Kernel 4c: greedy + score threshold + stable rank<100 + det write.
// grid(2), block(256). Warp 0 runs the register/ballot greedy over the
// global bitmatrix (kept words identical in every lane).
// ---------------------------------------------------------------------------
__global__ void finish_kernel(const float* __restrict__ boxes,
                              const float* __restrict__ scores,
                              float* __restrict__ det) {
    int n = blockIdx.x;
    int t = threadIdx.x;
    int gid = n * NR + t;

    __shared__ unsigned int keptw[8];
    __shared__ float smask[NR];

    if (t < 32) {
        unsigned kept[8];
        #pragma unroll
        for (int w = 0; w < 8; w++) kept[w] = 0u;
        #pragma unroll
        for (int w = 0; w < 8; w++) {
            int i = w * 32 + t;
            uint4 q0 = *(const uint4*)&g_supmask[(n * NR + i) * 8];
            uint4 q1 = *(const uint4*)&g_supmask[(n * NR + i) * 8 + 4];
            unsigned rw[8] = {q0.x, q0.y, q0.z, q0.w, q1.x, q1.y, q1.z, q1.w};
            unsigned m = 0;
            #pragma unroll
            for (int w2 = 0; w2 < 8; w2++)
                if (w2 < w) m |= rw[w2] & kept[w2];
            bool sup_prev = (m != 0u);
            unsigned myw = rw[w];
            unsigned kw = 0u;
            #pragma unroll
            for (int k = 0; k < 32; k++) {
                bool keep_me = (!sup_prev) && ((myw & kw) == 0u);
                unsigned b = __ballot_sync(0xffffffffu, keep_me);
                kw |= (b & (1u << k));
            }
            kept[w] = kw;
        }
        #pragma unroll
        for (int w = 0; w < 8; w++)
            if (t == w) keptw[w] = kept[w];
    }

    float s_i = scores[gid];
    int rk = g_rank[gid];
    __syncthreads();

    bool kp = (keptw[rk >> 5] >> (rk & 31)) & 1u;
    kp = kp && (s_i > SCORE_TH);
    smask[t] = kp ? s_i : -INFINITY;
    __syncthreads();

    int rank2 = 0;
    float mi = smask[t];
    #pragma unroll 8
    for (int j = 0; j < NR; j++) {
        float mj = smask[j];
        rank2 += (mj > mi) || (mj == mi && j < t);
    }
    kp = kp && (rank2 < MAX_DET);

    const float* bsrc = boxes + (size_t)gid * 4;
    float* drow = det + (size_t)gid * 6;
    drow[0] = bsrc[0]; drow[1] = bsrc[1];
    drow[2] = bsrc[2]; drow[3] = bsrc[3];
    drow[4] = s_i;
    drow[5] = kp ? 1.0f : 0.0f;
}

// ---------------------------------------------------------------------------
extern "C" void kernel_launch(void* const* d_in, const int* in_sizes, int n_in,
                              void* d_out, int out_size) {
    const float* features = (const float*)d_in[0];
    const float* proposals = (const float*)d_in[1];
    const float* gt_boxes = (const float*)d_in[2];
    // d_in[3] = gt_classes (unused by reference)
    const float* W_cls = (const float*)d_in[4];
    const float* b_cls = (const float*)d_in[5];
    const float* W_box = (const float*)d_in[6];
    const float* b_box = (const float*)d_in[7];

    float* out = (float*)d_out;
    float* det = out;                          // 2*256*6 = 3072
    float* out_idx = out + NIMG * NR * 6;      // 512
    float* out_lbl = out_idx + NIMG * NR;      // 512

    float* featvec; cudaGetSymbolAddress((void**)&featvec, g_featvec);
    float* boxes;   cudaGetSymbolAddress((void**)&boxes, g_boxes);
    float* scores;  cudaGetSymbolAddress((void**)&scores, g_scores);

    const int ROI_SMEM = FH * FW * 8 * (int)sizeof(float);         // 128000 B
    const int GEMM_SMEM = (MTILE * KSLICE + KSLICE * NCOL) * 4;    // 65536 B
    cudaFuncSetAttribute(roi_kernel,
                         cudaFuncAttributeMaxDynamicSharedMemorySize, ROI_SMEM);
    cudaFuncSetAttribute(gemm_kernel,
                         cudaFuncAttributeMaxDynamicSharedMemorySize, GEMM_SMEM);

    weight_kernel<<<dim3(8, NIMG), 256>>>(proposals, gt_boxes, out_idx, out_lbl);
    roi_kernel<<<dim3(FC / 8, NIMG), 256, ROI_SMEM>>>(features, featvec);
    gemm_kernel<<<dim3(NPROP / MTILE, KSPLIT), 256, GEMM_SMEM>>>(featvec,
                                                                 W_cls, W_box);
    reduce_kernel<<<NPROP, 96>>>(proposals, b_cls, b_box, boxes, scores);
    sort_kernel<<<NIMG, NR>>>(boxes, scores);
    iou_kernel<<<dim3(8, NIMG), 256>>>();
    finish_kernel<<<NIMG, NR>>>(boxes, scores, det);
}

// round 10
// speedup vs baseline: 1.8010x; 1.2014x over previous
#include <cuda_runtime.h>
#include <math.h>

#define IMG_H 800.0f
#define IMG_W 1280.0f
#define FSCALE (1.0f/16.0f)
#define PP 14
#define NUM_CLASSES 80
#define SCORE_TH 0.05f
#define NMS_TH 0.5f
#define MAX_DET 100
#define IOU_TH 0.5f
#define SCALE_CLAMP 4.135166556742356f
#define FH 50
#define FW 80
#define FC 1024
#define NIMG 2
#define NR 256
#define NGT 64
#define NPROP (NIMG * NR)          // 512
#define NCOL 96                    // padded output cols: 0..80 cls, 81..84 box
#define KSPLIT 8
#define KSLICE (FC / KSPLIT)       // 128
#define MTILE 32

// Scratch (device globals; no allocation allowed)
__device__ float g_featvec[NPROP * FC];
__device__ float g_boxes[NPROP * 4];
__device__ float g_scores[NPROP];
__device__ float g_wy[NPROP * FH];
__device__ float g_wx[NPROP * FW];
__device__ int   g_bnd[NPROP * 4];               // ylo,yhi,xlo,xhi
__device__ float g_part[KSPLIT * NPROP * NCOL];  // split-K partials
__device__ float g_sboxes[NPROP * 4];            // score-sorted boxes
__device__ int   g_rank[NPROP];                  // sorted position per proposal
__device__ unsigned int g_supmask[NPROP * 8];    // suppression bitmatrix

// ---------------------------------------------------------------------------
// Kernel 1: fused match + separable ROIAlign weight tables.
// grid(8, 2): 32 boxes per block, block(256). Per box: sub 0 = y-table,
// sub 1 = x-table, sub 2 = GT matching (all independent).
// ---------------------------------------------------------------------------
__global__ void weight_kernel(const float* __restrict__ prop,
                              const float* __restrict__ gt,
                              float* __restrict__ out_idx,
                              float* __restrict__ out_lbl) {
    int n = blockIdx.y;
    int b0 = blockIdx.x * 32;
    int t = threadIdx.x;

    __shared__ float wy[32 * FH];
    __shared__ float wx[32 * FW];

    for (int i = t; i < 32 * FH; i += 256) wy[i] = 0.0f;
    for (int i = t; i < 32 * FW; i += 256) wx[i] = 0.0f;
    __syncthreads();

    int b = t >> 3;          // box within block
    int sub = t & 7;
    int box = b0 + b;
    const float* p = prop + (n * NR + box) * 4;

    if (sub == 0) {
        float y1 = p[1] * FSCALE, y2 = p[3] * FSCALE;
        float bh = (y2 - y1) * (1.0f / (float)PP);
        int lo = FH, hi = 0;
        for (int py = 0; py < PP; py++) {
            float gy = y1 + ((float)py + 0.5f) * bh - 0.5f;
            gy = fminf(fmaxf(gy, 0.0f), (float)(FH - 1));
            float y0 = floorf(gy);
            int y0i = (int)y0;
            int y1i = min(y0i + 1, FH - 1);
            float ly = gy - y0;
            wy[b * FH + y0i] += 1.0f - ly;
            wy[b * FH + y1i] += ly;
            lo = min(lo, y0i);
            hi = max(hi, y1i);
        }
        g_bnd[(n * NR + box) * 4 + 0] = lo;
        g_bnd[(n * NR + box) * 4 + 1] = hi;
    } else if (sub == 1) {
        float x1 = p[0] * FSCALE, x2 = p[2] * FSCALE;
        float bw = (x2 - x1) * (1.0f / (float)PP);
        int lo = FW, hi = 0;
        for (int px = 0; px < PP; px++) {
            float gx = x1 + ((float)px + 0.5f) * bw - 0.5f;
            gx = fminf(fmaxf(gx, 0.0f), (float)(FW - 1));
            float x0 = floorf(gx);
            int x0i = (int)x0;
            int x1i = min(x0i + 1, FW - 1);
            float lx = gx - x0;
            wx[b * FW + x0i] += 1.0f - lx;
            wx[b * FW + x1i] += lx;
            lo = min(lo, x0i);
            hi = max(hi, x1i);
        }
        g_bnd[(n * NR + box) * 4 + 2] = lo;
        g_bnd[(n * NR + box) * 4 + 3] = hi;
    } else if (sub == 2) {
        float px1 = p[0], py1 = p[1], px2 = p[2], py2 = p[3];
        float pa = (px2 - px1) * (py2 - py1);
        float best = -1.0f;
        int bi = 0;
        for (int g = 0; g < NGT; g++) {
            const float* gb = gt + (n * NGT + g) * 4;
            float gx1 = gb[0], gy1 = gb[1], gx2 = gb[2], gy2 = gb[3];
            float ga = (gx2 - gx1) * (gy2 - gy1);
            float lx = fmaxf(gx1, px1), ly = fmaxf(gy1, py1);
            float rx = fminf(gx2, px2), ry = fminf(gy2, py2);
            float w = fmaxf(rx - lx, 0.0f), h = fmaxf(ry - ly, 0.0f);
            float inter = w * h;
            float iou = inter / fmaxf(ga + pa - inter, 1e-9f);
            if (iou > best) { best = iou; bi = g; }
        }
        out_idx[n * NR + box] = (float)bi;
        out_lbl[n * NR + box] = (best >= IOU_TH) ? 1.0f : 0.0f;
    }
    __syncthreads();

    for (int i = t; i < 32 * FH; i += 256) g_wy[(n * NR + b0) * FH + i] = wy[i];
    for (int i = t; i < 32 * FW; i += 256) g_wx[(n * NR + b0) * FW + i] = wx[i];
}

// ---------------------------------------------------------------------------
// Kernel 2: ROIAlign, one block per box. grid(256, 2), block(256).
// Thread t owns channels [4t, 4t+4). The box's weight tables live in smem
// (uniform broadcast reads); feature reads are coalesced LDG.128 runs of
// 4KB/cell from the L2-resident feature map. Accumulation order per channel
// (y outer, x inner) identical to previous versions -> bit-identical output.
// ---------------------------------------------------------------------------
__global__ void roi_kernel(const float* __restrict__ feat,
                           float* __restrict__ featvec) {
    __shared__ float wyS[FH];
    __shared__ float wxS[FW];
    __shared__ int bndS[4];

    int box = blockIdx.x;
    int n = blockIdx.y;
    int gid = n * NR + box;
    int t = threadIdx.x;

    if (t < FH) wyS[t] = g_wy[gid * FH + t];
    if (t >= 64 && t < 64 + FW) wxS[t - 64] = g_wx[gid * FW + (t - 64)];
    if (t >= 160 && t < 164) bndS[t - 160] = g_bnd[gid * 4 + (t - 160)];
    __syncthreads();

    int ylo = bndS[0], yhi = bndS[1], xlo = bndS[2], xhi = bndS[3];

    const float4* f = (const float4*)(feat + (size_t)n * FH * FW * FC) + t;
    float4 acc = make_float4(0.f, 0.f, 0.f, 0.f);

    for (int y = ylo; y <= yhi; y++) {
        float wyv = wyS[y];
        const float4* rowp = f + (size_t)(y * FW) * (FC / 4);
        for (int x = xlo; x <= xhi; x++) {
            float w = wyv * wxS[x];
            float4 v = rowp[(size_t)x * (FC / 4)];
            acc.x += w * v.x;
            acc.y += w * v.y;
            acc.z += w * v.z;
            acc.w += w * v.w;
        }
    }
    const float inv = 1.0f / (float)(PP * PP);
    acc.x *= inv; acc.y *= inv; acc.z *= inv; acc.w *= inv;
    ((float4*)featvec)[(size_t)gid * (FC / 4) + t] = acc;
}

// ---------------------------------------------------------------------------
// Kernel 3a: head GEMM, smem-tiled + split-K.
// grid(16, 8) = (M-tile of 32 props, K-slice of 128), block(256), 64KB smem.
// ---------------------------------------------------------------------------
__global__ void gemm_kernel(const float* __restrict__ featvec,
                            const float* __restrict__ Wc,
                            const float* __restrict__ Wb) {
    extern __shared__ float sm[];
    float* sfS = sm;                 // 32*128
    float* wS = sm + MTILE * KSLICE; // 128*96

    int t = threadIdx.x;
    int p0 = blockIdx.x * MTILE;
    int k0 = blockIdx.y * KSLICE;

    for (int i = t; i < MTILE * KSLICE; i += 256) {
        int p = i >> 7;          // /128
        int k = i & (KSLICE - 1);
        sfS[i] = featvec[(size_t)(p0 + p) * FC + k0 + k];
    }
    for (int i = t; i < KSLICE * NCOL; i += 256) {
        int r = i / NCOL;
        int c = i - r * NCOL;
        float v = 0.0f;
        if (c < NUM_CLASSES + 1) v = Wc[(size_t)(k0 + r) * (NUM_CLASSES + 1) + c];
        else if (c < NUM_CLASSES + 5) v = Wb[(size_t)(k0 + r) * 4 + (c - 81)];
        wS[i] = v;
    }
    __syncthreads();

    int colg = t & 31;
    int propg = t >> 5;              // 0..7
    const float* sfp = sfS + (propg * 4) * KSLICE;

    float a00 = 0.f, a01 = 0.f, a02 = 0.f;
    float a10 = 0.f, a11 = 0.f, a12 = 0.f;
    float a20 = 0.f, a21 = 0.f, a22 = 0.f;
    float a30 = 0.f, a31 = 0.f, a32 = 0.f;

    #pragma unroll 4
    for (int k = 0; k < KSLICE; k++) {
        float w0 = wS[k * NCOL + colg];
        float w1 = wS[k * NCOL + colg + 32];
        float w2 = wS[k * NCOL + colg + 64];
        float s0 = sfp[k];
        float s1 = sfp[KSLICE + k];
        float s2 = sfp[2 * KSLICE + k];
        float s3 = sfp[3 * KSLICE + k];
        a00 += s0 * w0; a01 += s0 * w1; a02 += s0 * w2;
        a10 += s1 * w0; a11 += s1 * w1; a12 += s1 * w2;
        a20 += s2 * w0; a21 += s2 * w1; a22 += s2 * w2;
        a30 += s3 * w0; a31 += s3 * w1; a32 += s3 * w2;
    }

    float* op = g_part + (size_t)blockIdx.y * NPROP * NCOL +
                (size_t)(p0 + propg * 4) * NCOL + colg;
    op[0] = a00; op[32] = a01; op[64] = a02;
    op += NCOL; op[0] = a10; op[32] = a11; op[64] = a12;
    op += NCOL; op[0] = a20; op[32] = a21; op[64] = a22;
    op += NCOL; op[0] = a30; op[32] = a31; op[64] = a32;
}

// ---------------------------------------------------------------------------
// Kernel 3b: reduce split-K partials + bias, softmax fg score, box decode.
// grid(512) one block per proposal, block(96).
// ---------------------------------------------------------------------------
__global__ void reduce_kernel(const float* __restrict__ prop,
                              const float* __restrict__ bc,
                              const float* __restrict__ bb,
                              float* __restrict__ boxes,
                              float* __restrict__ scores) {
    int gid = blockIdx.x;
    int t = threadIdx.x;
    __shared__ float slog[NUM_CLASSES + 5];

    if (t < NUM_CLASSES + 5) {
        float s = 0.0f;
        #pragma unroll
        for (int ks = 0; ks < KSPLIT; ks++)
            s += g_part[(size_t)ks * NPROP * NCOL + (size_t)gid * NCOL + t];
        if (t < NUM_CLASSES + 1) s += bc[t];
        else s += bb[t - 81];
        slog[t] = s;
    }
    __syncthreads();

    if (t == 0) {
        float m = -INFINITY;
        for (int c = 0; c <= NUM_CLASSES; c++) m = fmaxf(m, slog[c]);
        float ssum = 0.0f;
        float fg = -INFINITY;
        for (int c = 0; c <= NUM_CLASSES; c++) {
            float e = expf(slog[c] - m);
            ssum += e;
            if (c < NUM_CLASSES) fg = fmaxf(fg, e);
        }
        scores[gid] = fg / ssum;

        const float* p = prop + (size_t)gid * 4;
        float px1 = p[0], py1 = p[1], px2 = p[2], py2 = p[3];
        float wdt = px2 - px1, hgt = py2 - py1;
        float cx = px1 + 0.5f * wdt, cy = py1 + 0.5f * hgt;
        float dx = slog[81] * 0.1f;
        float dy = slog[82] * 0.1f;
        float dw = fminf(slog[83] * 0.2f, SCALE_CLAMP);
        float dh = fminf(slog[84] * 0.2f, SCALE_CLAMP);
        float pcx = dx * wdt + cx;
        float pcy = dy * hgt + cy;
        float pw = expf(dw) * wdt;
        float ph = expf(dh) * hgt;
        float* ob = boxes + (size_t)gid * 4;
        ob[0] = fminf(fmaxf(pcx - 0.5f * pw, 0.0f), IMG_W);
        ob[1] = fminf(fmaxf(pcy - 0.5f * ph, 0.0f), IMG_H);
        ob[2] = fminf(fmaxf(pcx + 0.5f * pw, 0.0f), IMG_W);
        ob[3] = fminf(fmaxf(pcy + 0.5f * ph, 0.0f), IMG_H);
    }
}

// ---------------------------------------------------------------------------
// Kernel 4a: stable descending sort rank + sorted box gather. grid(2), b(256).
// ---------------------------------------------------------------------------
__global__ void sort_kernel(const float* __restrict__ boxes,
                            const float* __restrict__ scores) {
    int n = blockIdx.x;
    int t = threadIdx.x;
    int gid = n * NR + t;

    __shared__ float ss[NR];
    __shared__ int order[NR];

    float s_i = scores[gid];
    ss[t] = s_i;
    __syncthreads();

    int rk = 0;
    #pragma unroll 8
    for (int j = 0; j < NR; j++) {
        float sj = ss[j];
        rk += (sj > s_i) || (sj == s_i && j < t);
    }
    g_rank[gid] = rk;
    order[rk] = t;
    __syncthreads();

    ((float4*)g_sboxes)[gid] = ((const float4*)boxes)[n * NR + order[t]];
}

// ---------------------------------------------------------------------------
// Kernel 4b: IoU suppression bitmatrix. grid(8, 2), block(256).
// Thread = one 32-bit word: row r = bx*32 + t/8, word w = t%8 (coalesced STG).
// ---------------------------------------------------------------------------
__global__ void iou_kernel() {
    __shared__ float4 sb[NR];
    int n = blockIdx.y;
    int t = threadIdx.x;

    for (int i = t; i < NR; i += 256) sb[i] = ((const float4*)g_sboxes)[n * NR + i];
    __syncthreads();

    int r = blockIdx.x * 32 + (t >> 3);
    int w = t & 7;

    float4 a = sb[r];
    float aa = (a.z - a.x) * (a.w - a.y);
    unsigned int word = 0;
    #pragma unroll 8
    for (int k = 0; k < 32; k++) {
        float4 b = sb[w * 32 + k];
        float ba = (b.z - b.x) * (b.w - b.y);
        float lx = fmaxf(a.x, b.x), ly = fmaxf(a.y, b.y);
        float rx = fminf(a.z, b.z), ry = fminf(a.w, b.w);
        float ww = fmaxf(rx - lx, 0.0f), hh = fmaxf(ry - ly, 0.0f);
        float inter = ww * hh;
        float u = fmaxf(aa + ba - inter, 1e-9f);
        if (inter > NMS_TH * u) word |= (1u << k);
    }
    g_supmask[(n * NR + r) * 8 + w] = word;
}

// ---------------------------------------------------------------------------
// Kernel 4c: greedy + score threshold + stable rank<100 + det write.
// grid(2), block(256). Warp 0 runs the register/ballot greedy.
// ---------------------------------------------------------------------------
__global__ void finish_kernel(const float* __restrict__ boxes,
                              const float* __restrict__ scores,
                              float* __restrict__ det) {
    int n = blockIdx.x;
    int t = threadIdx.x;
    int gid = n * NR + t;

    __shared__ unsigned int keptw[8];
    __shared__ float smask[NR];

    if (t < 32) {
        unsigned kept[8];
        #pragma unroll
        for (int w = 0; w < 8; w++) kept[w] = 0u;
        #pragma unroll
        for (int w = 0; w < 8; w++) {
            int i = w * 32 + t;
            uint4 q0 = *(const uint4*)&g_supmask[(n * NR + i) * 8];
            uint4 q1 = *(const uint4*)&g_supmask[(n * NR + i) * 8 + 4];
            unsigned rw[8] = {q0.x, q0.y, q0.z, q0.w, q1.x, q1.y, q1.z, q1.w};
            unsigned m = 0;
            #pragma unroll
            for (int w2 = 0; w2 < 8; w2++)
                if (w2 < w) m |= rw[w2] & kept[w2];
            bool sup_prev = (m != 0u);
            unsigned myw = rw[w];
            unsigned kw = 0u;
            #pragma unroll
            for (int k = 0; k < 32; k++) {
                bool keep_me = (!sup_prev) && ((myw & kw) == 0u);
                unsigned b = __ballot_sync(0xffffffffu, keep_me);
                kw |= (b & (1u << k));
            }
            kept[w] = kw;
        }
        #pragma unroll
        for (int w = 0; w < 8; w++)
            if (t == w) keptw[w] = kept[w];
    }

    float s_i = scores[gid];
    int rk = g_rank[gid];
    __syncthreads();

    bool kp = (keptw[rk >> 5] >> (rk & 31)) & 1u;
    kp = kp && (s_i > SCORE_TH);
    smask[t] = kp ? s_i : -INFINITY;
    __syncthreads();

    int rank2 = 0;
    float mi = smask[t];
    #pragma unroll 8
    for (int j = 0; j < NR; j++) {
        float mj = smask[j];
        rank2 += (mj > mi) || (mj == mi && j < t);
    }
    kp = kp && (rank2 < MAX_DET);

    const float* bsrc = boxes + (size_t)gid * 4;
    float* drow = det + (size_t)gid * 6;
    drow[0] = bsrc[0]; drow[1] = bsrc[1];
    drow[2] = bsrc[2]; drow[3] = bsrc[3];
    drow[4] = s_i;
    drow[5] = kp ? 1.0f : 0.0f;
}

// ---------------------------------------------------------------------------
extern "C" void kernel_launch(void* const* d_in, const int* in_sizes, int n_in,
                              void* d_out, int out_size) {
    const float* features = (const float*)d_in[0];
    const float* proposals = (const float*)d_in[1];
    const float* gt_boxes = (const float*)d_in[2];
    // d_in[3] = gt_classes (unused by reference)
    const float* W_cls = (const float*)d_in[4];
    const float* b_cls = (const float*)d_in[5];
    const float* W_box = (const float*)d_in[6];
    const float* b_box = (const float*)d_in[7];

    float* out = (float*)d_out;
    float* det = out;                          // 2*256*6 = 3072
    float* out_idx = out + NIMG * NR * 6;      // 512
    float* out_lbl = out_idx + NIMG * NR;      // 512

    float* featvec; cudaGetSymbolAddress((void**)&featvec, g_featvec);
    float* boxes;   cudaGetSymbolAddress((void**)&boxes, g_boxes);
    float* scores;  cudaGetSymbolAddress((void**)&scores, g_scores);

    const int GEMM_SMEM = (MTILE * KSLICE + KSLICE * NCOL) * 4;    // 65536 B
    cudaFuncSetAttribute(gemm_kernel,
                         cudaFuncAttributeMaxDynamicSharedMemorySize, GEMM_SMEM);

    weight_kernel<<<dim3(8, NIMG), 256>>>(proposals, gt_boxes, out_idx, out_lbl);
    roi_kernel<<<dim3(NR, NIMG), 256>>>(features, featvec);
    gemm_kernel<<<dim3(NPROP / MTILE, KSPLIT), 256, GEMM_SMEM>>>(featvec,
                                                                 W_cls, W_box);
    reduce_kernel<<<NPROP, 96>>>(proposals, b_cls, b_box, boxes, scores);
    sort_kernel<<<NIMG, NR>>>(boxes, scores);
    iou_kernel<<<dim3(8, NIMG), 256>>>();
    finish_kernel<<<NIMG, NR>>>(boxes, scores, det);
}

// round 11
// speedup vs baseline: 2.1095x; 1.1713x over previous
#include <cuda_runtime.h>
#include <math.h>

#define IMG_H 800.0f
#define IMG_W 1280.0f
#define FSCALE (1.0f/16.0f)
#define PP 14
#define NUM_CLASSES 80
#define SCORE_TH 0.05f
#define NMS_TH 0.5f
#define MAX_DET 100
#define IOU_TH 0.5f
#define SCALE_CLAMP 4.135166556742356f
#define FH 50
#define FW 80
#define FC 1024
#define NIMG 2
#define NR 256
#define NGT 64
#define NPROP (NIMG * NR)          // 512
#define NCOL 96                    // padded output cols: 0..80 cls, 81..84 box
#define KSPLIT 8
#define KSLICE (FC / KSPLIT)       // 128
#define MTILE 32

// Scratch (device globals; no allocation allowed)
__device__ float g_featvec[NPROP * FC];
__device__ float g_boxes[NPROP * 4];
__device__ float g_scores[NPROP];
__device__ float g_wy[NPROP * FH];
__device__ float g_wx[NPROP * FW];
__device__ int   g_bnd[NPROP * 4];               // ylo,yhi,xlo,xhi
__device__ float g_part[KSPLIT * NPROP * NCOL];  // split-K partials
__device__ float g_sboxes[NPROP * 4];            // score-sorted boxes
__device__ int   g_rank[NPROP];                  // sorted position per proposal
__device__ unsigned int g_supmask[NPROP * 8];    // suppression bitmatrix

// ---------------------------------------------------------------------------
// Kernel 1: fused match + separable ROIAlign weight tables.
// grid(8, 2): 32 boxes per block, block(256). Per box: sub 0 = y-table,
// sub 1 = x-table, sub 2 = GT matching (all independent).
// ---------------------------------------------------------------------------
__global__ void weight_kernel(const float* __restrict__ prop,
                              const float* __restrict__ gt,
                              float* __restrict__ out_idx,
                              float* __restrict__ out_lbl) {
    int n = blockIdx.y;
    int b0 = blockIdx.x * 32;
    int t = threadIdx.x;

    __shared__ float wy[32 * FH];
    __shared__ float wx[32 * FW];

    for (int i = t; i < 32 * FH; i += 256) wy[i] = 0.0f;
    for (int i = t; i < 32 * FW; i += 256) wx[i] = 0.0f;
    __syncthreads();

    int b = t >> 3;          // box within block
    int sub = t & 7;
    int box = b0 + b;
    const float* p = prop + (n * NR + box) * 4;

    if (sub == 0) {
        float y1 = p[1] * FSCALE, y2 = p[3] * FSCALE;
        float bh = (y2 - y1) * (1.0f / (float)PP);
        int lo = FH, hi = 0;
        for (int py = 0; py < PP; py++) {
            float gy = y1 + ((float)py + 0.5f) * bh - 0.5f;
            gy = fminf(fmaxf(gy, 0.0f), (float)(FH - 1));
            float y0 = floorf(gy);
            int y0i = (int)y0;
            int y1i = min(y0i + 1, FH - 1);
            float ly = gy - y0;
            wy[b * FH + y0i] += 1.0f - ly;
            wy[b * FH + y1i] += ly;
            lo = min(lo, y0i);
            hi = max(hi, y1i);
        }
        g_bnd[(n * NR + box) * 4 + 0] = lo;
        g_bnd[(n * NR + box) * 4 + 1] = hi;
    } else if (sub == 1) {
        float x1 = p[0] * FSCALE, x2 = p[2] * FSCALE;
        float bw = (x2 - x1) * (1.0f / (float)PP);
        int lo = FW, hi = 0;
        for (int px = 0; px < PP; px++) {
            float gx = x1 + ((float)px + 0.5f) * bw - 0.5f;
            gx = fminf(fmaxf(gx, 0.0f), (float)(FW - 1));
            float x0 = floorf(gx);
            int x0i = (int)x0;
            int x1i = min(x0i + 1, FW - 1);
            float lx = gx - x0;
            wx[b * FW + x0i] += 1.0f - lx;
            wx[b * FW + x1i] += lx;
            lo = min(lo, x0i);
            hi = max(hi, x1i);
        }
        g_bnd[(n * NR + box) * 4 + 2] = lo;
        g_bnd[(n * NR + box) * 4 + 3] = hi;
    } else if (sub == 2) {
        float px1 = p[0], py1 = p[1], px2 = p[2], py2 = p[3];
        float pa = (px2 - px1) * (py2 - py1);
        float best = -1.0f;
        int bi = 0;
        for (int g = 0; g < NGT; g++) {
            const float* gb = gt + (n * NGT + g) * 4;
            float gx1 = gb[0], gy1 = gb[1], gx2 = gb[2], gy2 = gb[3];
            float ga = (gx2 - gx1) * (gy2 - gy1);
            float lx = fmaxf(gx1, px1), ly = fmaxf(gy1, py1);
            float rx = fminf(gx2, px2), ry = fminf(gy2, py2);
            float w = fmaxf(rx - lx, 0.0f), h = fmaxf(ry - ly, 0.0f);
            float inter = w * h;
            float iou = inter / fmaxf(ga + pa - inter, 1e-9f);
            if (iou > best) { best = iou; bi = g; }
        }
        out_idx[n * NR + box] = (float)bi;
        out_lbl[n * NR + box] = (best >= IOU_TH) ? 1.0f : 0.0f;
    }
    __syncthreads();

    for (int i = t; i < 32 * FH; i += 256) g_wy[(n * NR + b0) * FH + i] = wy[i];
    for (int i = t; i < 32 * FW; i += 256) g_wx[(n * NR + b0) * FW + i] = wx[i];
}

// ---------------------------------------------------------------------------
// Kernel 2: ROIAlign, one block per box. grid(256, 2), block(256).
// Thread t owns channels [4t, 4t+4). Weight tables in smem (broadcast reads);
// feature reads are coalesced LDG.128. Inner x-loop unrolled 4x with FOUR
// independent accumulator sets -> 4x MLP, 4x shorter FFMA chains.
// ---------------------------------------------------------------------------
__global__ void roi_kernel(const float* __restrict__ feat,
                           float* __restrict__ featvec) {
    __shared__ float wyS[FH];
    __shared__ float wxS[FW];
    __shared__ int bndS[4];

    int box = blockIdx.x;
    int n = blockIdx.y;
    int gid = n * NR + box;
    int t = threadIdx.x;

    if (t < FH) wyS[t] = g_wy[gid * FH + t];
    if (t >= 64 && t < 64 + FW) wxS[t - 64] = g_wx[gid * FW + (t - 64)];
    if (t >= 160 && t < 164) bndS[t - 160] = g_bnd[gid * 4 + (t - 160)];
    __syncthreads();

    int ylo = bndS[0], yhi = bndS[1], xlo = bndS[2], xhi = bndS[3];

    const float4* f = (const float4*)(feat + (size_t)n * FH * FW * FC) + t;
    float4 aA = make_float4(0.f, 0.f, 0.f, 0.f);
    float4 aB = make_float4(0.f, 0.f, 0.f, 0.f);
    float4 aC = make_float4(0.f, 0.f, 0.f, 0.f);
    float4 aD = make_float4(0.f, 0.f, 0.f, 0.f);

    for (int y = ylo; y <= yhi; y++) {
        float wyv = wyS[y];
        const float4* rowp = f + (size_t)(y * FW) * (FC / 4);
        int x = xlo;
        for (; x + 3 <= xhi; x += 4) {
            float wa = wyv * wxS[x];
            float wb = wyv * wxS[x + 1];
            float wc = wyv * wxS[x + 2];
            float wd = wyv * wxS[x + 3];
            float4 va = rowp[(size_t)x * (FC / 4)];
            float4 vb = rowp[(size_t)(x + 1) * (FC / 4)];
            float4 vc = rowp[(size_t)(x + 2) * (FC / 4)];
            float4 vd = rowp[(size_t)(x + 3) * (FC / 4)];
            aA.x += wa * va.x; aA.y += wa * va.y; aA.z += wa * va.z; aA.w += wa * va.w;
            aB.x += wb * vb.x; aB.y += wb * vb.y; aB.z += wb * vb.z; aB.w += wb * vb.w;
            aC.x += wc * vc.x; aC.y += wc * vc.y; aC.z += wc * vc.z; aC.w += wc * vc.w;
            aD.x += wd * vd.x; aD.y += wd * vd.y; aD.z += wd * vd.z; aD.w += wd * vd.w;
        }
        for (; x <= xhi; x++) {
            float wa = wyv * wxS[x];
            float4 va = rowp[(size_t)x * (FC / 4)];
            aA.x += wa * va.x; aA.y += wa * va.y; aA.z += wa * va.z; aA.w += wa * va.w;
        }
    }
    const float inv = 1.0f / (float)(PP * PP);
    float4 acc;
    acc.x = ((aA.x + aB.x) + (aC.x + aD.x)) * inv;
    acc.y = ((aA.y + aB.y) + (aC.y + aD.y)) * inv;
    acc.z = ((aA.z + aB.z) + (aC.z + aD.z)) * inv;
    acc.w = ((aA.w + aB.w) + (aC.w + aD.w)) * inv;
    ((float4*)featvec)[(size_t)gid * (FC / 4) + t] = acc;
}

// ---------------------------------------------------------------------------
// Kernel 3a: head GEMM, smem-tiled + split-K.
// grid(16, 8) = (M-tile of 32 props, K-slice of 128), block(256), 64KB smem.
// ---------------------------------------------------------------------------
__global__ void gemm_kernel(const float* __restrict__ featvec,
                            const float* __restrict__ Wc,
                            const float* __restrict__ Wb) {
    extern __shared__ float sm[];
    float* sfS = sm;                 // 32*128
    float* wS = sm + MTILE * KSLICE; // 128*96

    int t = threadIdx.x;
    int p0 = blockIdx.x * MTILE;
    int k0 = blockIdx.y * KSLICE;

    for (int i = t; i < MTILE * KSLICE; i += 256) {
        int p = i >> 7;          // /128
        int k = i & (KSLICE - 1);
        sfS[i] = featvec[(size_t)(p0 + p) * FC + k0 + k];
    }
    for (int i = t; i < KSLICE * NCOL; i += 256) {
        int r = i / NCOL;
        int c = i - r * NCOL;
        float v = 0.0f;
        if (c < NUM_CLASSES + 1) v = Wc[(size_t)(k0 + r) * (NUM_CLASSES + 1) + c];
        else if (c < NUM_CLASSES + 5) v = Wb[(size_t)(k0 + r) * 4 + (c - 81)];
        wS[i] = v;
    }
    __syncthreads();

    int colg = t & 31;
    int propg = t >> 5;              // 0..7
    const float* sfp = sfS + (propg * 4) * KSLICE;

    float a00 = 0.f, a01 = 0.f, a02 = 0.f;
    float a10 = 0.f, a11 = 0.f, a12 = 0.f;
    float a20 = 0.f, a21 = 0.f, a22 = 0.f;
    float a30 = 0.f, a31 = 0.f, a32 = 0.f;

    #pragma unroll 4
    for (int k = 0; k < KSLICE; k++) {
        float w0 = wS[k * NCOL + colg];
        float w1 = wS[k * NCOL + colg + 32];
        float w2 = wS[k * NCOL + colg + 64];
        float s0 = sfp[k];
        float s1 = sfp[KSLICE + k];
        float s2 = sfp[2 * KSLICE + k];
        float s3 = sfp[3 * KSLICE + k];
        a00 += s0 * w0; a01 += s0 * w1; a02 += s0 * w2;
        a10 += s1 * w0; a11 += s1 * w1; a12 += s1 * w2;
        a20 += s2 * w0; a21 += s2 * w1; a22 += s2 * w2;
        a30 += s3 * w0; a31 += s3 * w1; a32 += s3 * w2;
    }

    float* op = g_part + (size_t)blockIdx.y * NPROP * NCOL +
                (size_t)(p0 + propg * 4) * NCOL + colg;
    op[0] = a00; op[32] = a01; op[64] = a02;
    op += NCOL; op[0] = a10; op[32] = a11; op[64] = a12;
    op += NCOL; op[0] = a20; op[32] = a21; op[64] = a22;
    op += NCOL; op[0] = a30; op[32] = a31; op[64] = a32;
}

// ---------------------------------------------------------------------------
// Kernel 3b: warp-per-proposal reduce + softmax + decode. grid(64), b(256).
// Lane l owns cols {l, l+32, l+64}; g_part reads coalesced (96 contiguous
// floats per warp per split). Softmax via shfl tree reductions.
// ---------------------------------------------------------------------------
__global__ void reduce_kernel(const float* __restrict__ prop,
                              const float* __restrict__ bc,
                              const float* __restrict__ bb,
                              float* __restrict__ boxes,
                              float* __restrict__ scores) {
    int wid = threadIdx.x >> 5;
    int lane = threadIdx.x & 31;
    int gid = blockIdx.x * 8 + wid;

    float v0 = 0.f, v1 = 0.f, v2 = 0.f;
    #pragma unroll
    for (int ks = 0; ks < KSPLIT; ks++) {
        const float* q = g_part + (size_t)ks * NPROP * NCOL + (size_t)gid * NCOL;
        v0 += q[lane];
        v1 += q[lane + 32];
        v2 += q[lane + 64];
    }
    int c2 = lane + 64;
    v0 += bc[lane];
    v1 += bc[lane + 32];
    if (c2 <= NUM_CLASSES) v2 += bc[c2];
    else if (c2 <= NUM_CLASSES + 4) v2 += bb[c2 - 81];

    // max over logits 0..80
    float m = fmaxf(fmaxf(v0, v1), (c2 <= NUM_CLASSES) ? v2 : -INFINITY);
    #pragma unroll
    for (int o = 16; o; o >>= 1) m = fmaxf(m, __shfl_xor_sync(0xffffffffu, m, o));

    float e0 = expf(v0 - m);
    float e1 = expf(v1 - m);
    float e2 = (c2 <= NUM_CLASSES) ? expf(v2 - m) : 0.0f;
    float ssum = e0 + e1 + e2;
    #pragma unroll
    for (int o = 16; o; o >>= 1) ssum += __shfl_xor_sync(0xffffffffu, ssum, o);

    float fg = fmaxf(e0, e1);                 // cols 0..63 all foreground
    if (c2 < NUM_CLASSES) fg = fmaxf(fg, e2); // cols 64..79
    #pragma unroll
    for (int o = 16; o; o >>= 1) fg = fmaxf(fg, __shfl_xor_sync(0xffffffffu, fg, o));

    float dx = __shfl_sync(0xffffffffu, v2, 17);   // col 81
    float dy = __shfl_sync(0xffffffffu, v2, 18);   // col 82
    float dwv = __shfl_sync(0xffffffffu, v2, 19);  // col 83
    float dhv = __shfl_sync(0xffffffffu, v2, 20);  // col 84

    if (lane == 0) {
        scores[gid] = fg / ssum;

        const float* p = prop + (size_t)gid * 4;
        float px1 = p[0], py1 = p[1], px2 = p[2], py2 = p[3];
        float wdt = px2 - px1, hgt = py2 - py1;
        float cx = px1 + 0.5f * wdt, cy = py1 + 0.5f * hgt;
        float ddx = dx * 0.1f;
        float ddy = dy * 0.1f;
        float ddw = fminf(dwv * 0.2f, SCALE_CLAMP);
        float ddh = fminf(dhv * 0.2f, SCALE_CLAMP);
        float pcx = ddx * wdt + cx;
        float pcy = ddy * hgt + cy;
        float pw = expf(ddw) * wdt;
        float ph = expf(ddh) * hgt;
        float* ob = boxes + (size_t)gid * 4;
        ob[0] = fminf(fmaxf(pcx - 0.5f * pw, 0.0f), IMG_W);
        ob[1] = fminf(fmaxf(pcy - 0.5f * ph, 0.0f), IMG_H);
        ob[2] = fminf(fmaxf(pcx + 0.5f * pw, 0.0f), IMG_W);
        ob[3] = fminf(fmaxf(pcy + 0.5f * ph, 0.0f), IMG_H);
    }
}

// ---------------------------------------------------------------------------
// Kernel 4a: stable descending sort rank + sorted box gather. grid(2), b(256).
// ---------------------------------------------------------------------------
__global__ void sort_kernel(const float* __restrict__ boxes,
                            const float* __restrict__ scores) {
    int n = blockIdx.x;
    int t = threadIdx.x;
    int gid = n * NR + t;

    __shared__ float ss[NR];
    __shared__ int order[NR];

    float s_i = scores[gid];
    ss[t] = s_i;
    __syncthreads();

    int rk = 0;
    #pragma unroll 8
    for (int j = 0; j < NR; j++) {
        float sj = ss[j];
        rk += (sj > s_i) || (sj == s_i && j < t);
    }
    g_rank[gid] = rk;
    order[rk] = t;
    __syncthreads();

    ((float4*)g_sboxes)[gid] = ((const float4*)boxes)[n * NR + order[t]];
}

// ---------------------------------------------------------------------------
// Kernel 4b: IoU suppression bitmatrix. grid(8, 2), block(256).
// Thread = one 32-bit word: row r = bx*32 + t/8, word w = t%8 (coalesced STG).
// ---------------------------------------------------------------------------
__global__ void iou_kernel() {
    __shared__ float4 sb[NR];
    int n = blockIdx.y;
    int t = threadIdx.x;

    for (int i = t; i < NR; i += 256) sb[i] = ((const float4*)g_sboxes)[n * NR + i];
    __syncthreads();

    int r = blockIdx.x * 32 + (t >> 3);
    int w = t & 7;

    float4 a = sb[r];
    float aa = (a.z - a.x) * (a.w - a.y);
    unsigned int word = 0;
    #pragma unroll 8
    for (int k = 0; k < 32; k++) {
        float4 b = sb[w * 32 + k];
        float ba = (b.z - b.x) * (b.w - b.y);
        float lx = fmaxf(a.x, b.x), ly = fmaxf(a.y, b.y);
        float rx = fminf(a.z, b.z), ry = fminf(a.w, b.w);
        float ww = fmaxf(rx - lx, 0.0f), hh = fmaxf(ry - ly, 0.0f);
        float inter = ww * hh;
        float u = fmaxf(aa + ba - inter, 1e-9f);
        if (inter > NMS_TH * u) word |= (1u << k);
    }
    g_supmask[(n * NR + r) * 8 + w] = word;
}

// ---------------------------------------------------------------------------
// Kernel 4c: greedy + score threshold + stable rank<100 + det write.
// grid(2), block(256). Warp 0 runs the register/ballot greedy.
// ---------------------------------------------------------------------------
__global__ void finish_kernel(const float* __restrict__ boxes,
                              const float* __restrict__ scores,
                              float* __restrict__ det) {
    int n = blockIdx.x;
    int t = threadIdx.x;
    int gid = n * NR + t;

    __shared__ unsigned int keptw[8];
    __shared__ float smask[NR];

    if (t < 32) {
        unsigned kept[8];
        #pragma unroll
        for (int w = 0; w < 8; w++) kept[w] = 0u;
        #pragma unroll
        for (int w = 0; w < 8; w++) {
            int i = w * 32 + t;
            uint4 q0 = *(const uint4*)&g_supmask[(n * NR + i) * 8];
            uint4 q1 = *(const uint4*)&g_supmask[(n * NR + i) * 8 + 4];
            unsigned rw[8] = {q0.x, q0.y, q0.z, q0.w, q1.x, q1.y, q1.z, q1.w};
            unsigned m = 0;
            #pragma unroll
            for (int w2 = 0; w2 < 8; w2++)
                if (w2 < w) m |= rw[w2] & kept[w2];
            bool sup_prev = (m != 0u);
            unsigned myw = rw[w];
            unsigned kw = 0u;
            #pragma unroll
            for (int k = 0; k < 32; k++) {
                bool keep_me = (!sup_prev) && ((myw & kw) == 0u);
                unsigned b = __ballot_sync(0xffffffffu, keep_me);
                kw |= (b & (1u << k));
            }
            kept[w] = kw;
        }
        #pragma unroll
        for (int w = 0; w < 8; w++)
            if (t == w) keptw[w] = kept[w];
    }

    float s_i = scores[gid];
    int rk = g_rank[gid];
    __syncthreads();

    bool kp = (keptw[rk >> 5] >> (rk & 31)) & 1u;
    kp = kp && (s_i > SCORE_TH);
    smask[t] = kp ? s_i : -INFINITY;
    __syncthreads();

    int rank2 = 0;
    float mi = smask[t];
    #pragma unroll 8
    for (int j = 0; j < NR; j++) {
        float mj = smask[j];
        rank2 += (mj > mi) || (mj == mi && j < t);
    }
    kp = kp && (rank2 < MAX_DET);

    const float* bsrc = boxes + (size_t)gid * 4;
    float* drow = det + (size_t)gid * 6;
    drow[0] = bsrc[0]; drow[1] = bsrc[1];
    drow[2] = bsrc[2]; drow[3] = bsrc[3];
    drow[4] = s_i;
    drow[5] = kp ? 1.0f : 0.0f;
}

// ---------------------------------------------------------------------------
extern "C" void kernel_launch(void* const* d_in, const int* in_sizes, int n_in,
                              void* d_out, int out_size) {
    const float* features = (const float*)d_in[0];
    const float* proposals = (const float*)d_in[1];
    const float* gt_boxes = (const float*)d_in[2];
    // d_in[3] = gt_classes (unused by reference)
    const float* W_cls = (const float*)d_in[4];
    const float* b_cls = (const float*)d_in[5];
    const float* W_box = (const float*)d_in[6];
    const float* b_box = (const float*)d_in[7];

    float* out = (float*)d_out;
    float* det = out;                          // 2*256*6 = 3072
    float* out_idx = out + NIMG * NR * 6;      // 512
    float* out_lbl = out_idx + NIMG * NR;      // 512

    float* featvec; cudaGetSymbolAddress((void**)&featvec, g_featvec);
    float* boxes;   cudaGetSymbolAddress((void**)&boxes, g_boxes);
    float* scores;  cudaGetSymbolAddress((void**)&scores, g_scores);

    const int GEMM_SMEM = (MTILE * KSLICE + KSLICE * NCOL) * 4;    // 65536 B
    cudaFuncSetAttribute(gemm_kernel,
                         cudaFuncAttributeMaxDynamicSharedMemorySize, GEMM_SMEM);

    weight_kernel<<<dim3(8, NIMG), 256>>>(proposals, gt_boxes, out_idx, out_lbl);
    roi_kernel<<<dim3(NR, NIMG), 256>>>(features, featvec);
    gemm_kernel<<<dim3(NPROP / MTILE, KSPLIT), 256, GEMM_SMEM>>>(featvec,
                                                                 W_cls, W_box);
    reduce_kernel<<<NPROP / 8, 256>>>(proposals, b_cls, b_box, boxes, scores);
    sort_kernel<<<NIMG, NR>>>(boxes, scores);
    iou_kernel<<<dim3(8, NIMG), 256>>>();
    finish_kernel<<<NIMG, NR>>>(boxes, scores, det);
}